// round 8
// baseline (speedup 1.0000x reference)
#include <cuda_runtime.h>
#include <math.h>

typedef unsigned long long ull;

#define NB 4
#define NC 128
#define NHW 4096
#define NG 32
#define NTD 512
#define SCALE_Q 0.088388347648318447f  /* 1/sqrt(128) */

// ------------------------- static scratch (no allocations) -------------------------
static __device__ float g_act [NB * NC * NHW];   // GN+SiLU activations (both GNs)
static __device__ float g_h1  [NB * NC * NHW];   // conv1 out + temb
static __device__ float g_h1T [NB * NHW * NC];   // h1 transposed [b][w][h][c], * 1/sqrt(C)
static __device__ float g_cbuf[NB * NC * NHW];   // cond 1x1 projection
static __device__ float g_h2  [NB * NC * NHW];   // h1 + embed (+ attn via atomics)
static __device__ float g_temb[NB * NC];
static __device__ float g_mean[NB * NG];
static __device__ float g_rstd[NB * NG];

// ------------------------- packed f32x2 helpers (sm_103a FFMA2) -------------------------
__device__ __forceinline__ void fma2(ull& d, ull a, ull b) {
    asm("fma.rn.f32x2 %0, %1, %2, %0;" : "+l"(d) : "l"(a), "l"(b));
}
__device__ __forceinline__ ull dup2(float x) {
    ull r;
    asm("mov.b64 %0, {%1, %2};" : "=l"(r) : "f"(x), "f"(x));
    return r;
}
__device__ __forceinline__ float2 unp2(ull v) {
    float2 r;
    asm("mov.b64 {%0, %1}, %2;" : "=f"(r.x), "=f"(r.y) : "l"(v));
    return r;
}
__device__ __forceinline__ float siluf(float x) { return x / (1.0f + __expf(-x)); }

// ------------------------- group-norm statistics: block per (b, g) -------------------------
__global__ void __launch_bounds__(256) gn_stats_k(const float* __restrict__ src,
                                                  float* __restrict__ mean,
                                                  float* __restrict__ rstd) {
    int bg = blockIdx.x;                 // b*32+g; group = 4 contiguous channels
    const float4* p = (const float4*)(src + bg * 16384);
    float s = 0.f, ss = 0.f;
    for (int i = threadIdx.x; i < 4096; i += 256) {
        float4 v = p[i];
        s  += v.x + v.y + v.z + v.w;
        ss += v.x * v.x + v.y * v.y + v.z * v.z + v.w * v.w;
    }
    for (int off = 16; off; off >>= 1) {
        s  += __shfl_down_sync(0xffffffffu, s,  off);
        ss += __shfl_down_sync(0xffffffffu, ss, off);
    }
    __shared__ float ws[8], wss[8];
    int wid = threadIdx.x >> 5, lane = threadIdx.x & 31;
    if (lane == 0) { ws[wid] = s; wss[wid] = ss; }
    __syncthreads();
    if (threadIdx.x == 0) {
        float ts = 0.f, tss = 0.f;
        for (int i = 0; i < 8; i++) { ts += ws[i]; tss += wss[i]; }
        float m = ts * (1.f / 16384.f);
        float var = tss * (1.f / 16384.f) - m * m;
        mean[bg] = m;
        rstd[bg] = rsqrtf(var + 1e-5f);
    }
}

// ------------------------- GN apply + SiLU (elementwise, float4) -------------------------
__global__ void __launch_bounds__(256) gn_apply_k(const float* __restrict__ src,
                                                  const float* __restrict__ mean,
                                                  const float* __restrict__ rstd,
                                                  const float* __restrict__ sc,
                                                  const float* __restrict__ bi,
                                                  float* __restrict__ dst) {
    int i = blockIdx.x * 256 + threadIdx.x;      // float4 index, total 524288
    int c  = (i >> 10) & 127;
    int bg = (i >> 17) * 32 + (c >> 2);
    float m = mean[bg], r = rstd[bg];
    float a = r * sc[c];
    float b = bi[c] - m * a;
    float4 v = ((const float4*)src)[i];
    v.x = siluf(v.x * a + b);
    v.y = siluf(v.y * a + b);
    v.z = siluf(v.z * a + b);
    v.w = siluf(v.w * a + b);
    ((float4*)dst)[i] = v;
}

// ------------------------- time embedding: temb = silu(t) @ W^T + b -------------------------
__global__ void __launch_bounds__(128) temb_k(const float* __restrict__ t,
                                              const float* __restrict__ mw,
                                              const float* __restrict__ mb,
                                              float* __restrict__ temb) {
    __shared__ float st[NTD];
    int b = blockIdx.x, tid = threadIdx.x;
    for (int k = tid; k < NTD; k += 128) st[k] = siluf(t[b * NTD + k]);
    __syncthreads();
    float acc = mb[tid];
    const float* wr = mw + tid * NTD;
#pragma unroll 8
    for (int k = 0; k < NTD; k++) acc += st[k] * wr[k];
    temb[b * NC + tid] = acc;
}

// ------------------------- 3x3 conv, pad 1, f32x2 inner, shifted smem copy ---------------
// MODE 0: +bias+temb; MODE 1: +bias+residual
template <int MODE>
__global__ void __launch_bounds__(256) conv3x3_k(const float* __restrict__ src,
                                                 const float* __restrict__ wgt,
                                                 const float* __restrict__ bias,
                                                 const float* __restrict__ temb,
                                                 const float* __restrict__ resid,
                                                 float* __restrict__ dst) {
    __shared__ __align__(16) float in_s[8 * 3 * 66];   // [ci][kh][wp]   (even-aligned pairs)
    __shared__ __align__(16) float in_o[8 * 3 * 66];   // shifted by 1: in_o[r][j] = in_s[r][j+1]
    __shared__ float wt_s[64 * 73];                    // [co][ci*9+k], stride 73
    int co0 = blockIdx.x * 64;
    int h   = blockIdx.y;
    int b   = blockIdx.z;
    int t   = threadIdx.x;
    int co_l = (t & 31) * 2;                // 2 output channels per thread
    int w0   = (t >> 5) * 8;                // 8 output columns, warp-uniform

    // weight decomposition: thread t loads 18 consecutive floats of the chunk's 4608
    int wco = t >> 2;                       // 0..63
    int wr0 = 18 * (t & 3);                 // 0..54, never crosses 72-row

    ull acc2[2][4];
#pragma unroll
    for (int c2 = 0; c2 < 2; c2++)
#pragma unroll
        for (int p = 0; p < 4; p++) acc2[c2][p] = 0ull;

    float wreg[18];
    float ireg[7];

    // ---- prefetch chunk 0 ----
    {
        const float* wp = wgt + (co0 + wco) * 1152 + wr0;
#pragma unroll
        for (int j = 0; j < 18; j++) wreg[j] = wp[j];
#pragma unroll
        for (int j = 0; j < 7; j++) {
            int idx = t + j * 256;
            float v = 0.f;
            if (idx < 1584) {
                int ci = idx / 198, r = idx % 198, kh = r / 66, wpp = r % 66;
                int hh = h - 1 + kh, wc = wpp - 1;
                if (hh >= 0 && hh < 64 && wc >= 0 && wc < 64)
                    v = src[((b * 128 + ci) * 64 + hh) * 64 + wc];
            }
            ireg[j] = v;
        }
    }

    for (int chunk = 0; chunk < 16; chunk++) {
        __syncthreads();
        // ---- store prefetched regs to smem ----
#pragma unroll
        for (int j = 0; j < 18; j++) wt_s[wco * 73 + wr0 + j] = wreg[j];
#pragma unroll
        for (int j = 0; j < 7; j++) {
            int idx = t + j * 256;
            if (idx < 1584) {
                in_s[idx] = ireg[j];
                int wpp = idx % 66;
                if (wpp > 0) in_o[idx - 1] = ireg[j];
            }
        }
        __syncthreads();
        // ---- prefetch chunk+1 ----
        if (chunk < 15) {
            int ci0n = (chunk + 1) * 8;
            const float* wp = wgt + (co0 + wco) * 1152 + ci0n * 9 + wr0;
#pragma unroll
            for (int j = 0; j < 18; j++) wreg[j] = wp[j];
#pragma unroll
            for (int j = 0; j < 7; j++) {
                int idx = t + j * 256;
                float v = 0.f;
                if (idx < 1584) {
                    int ci = idx / 198, r = idx % 198, kh = r / 66, wpp = r % 66;
                    int hh = h - 1 + kh, wc = wpp - 1;
                    if (hh >= 0 && hh < 64 && wc >= 0 && wc < 64)
                        v = src[((b * 128 + ci0n + ci) * 64 + hh) * 64 + wc];
                }
                ireg[j] = v;
            }
        }
        // ---- compute ----
#pragma unroll
        for (int ci = 0; ci < 8; ci++) {
#pragma unroll
            for (int kh = 0; kh < 3; kh++) {
                const ull* ep0 = (const ull*)&in_s[ci * 198 + kh * 66 + w0];
                const ull* ep1 = (const ull*)&in_o[ci * 198 + kh * 66 + w0];
                ull e0[5], e1[4];
#pragma unroll
                for (int p = 0; p < 5; p++) e0[p] = ep0[p];
#pragma unroll
                for (int p = 0; p < 4; p++) e1[p] = ep1[p];
#pragma unroll
                for (int c2 = 0; c2 < 2; c2++) {
                    const float* wr = &wt_s[(co_l + c2) * 73 + ci * 9 + kh * 3];
                    ull wad = dup2(wr[0]), wbd = dup2(wr[1]), wcd = dup2(wr[2]);
#pragma unroll
                    for (int p = 0; p < 4; p++) {
                        fma2(acc2[c2][p], wad, e0[p]);
                        fma2(acc2[c2][p], wbd, e1[p]);
                        fma2(acc2[c2][p], wcd, e0[p + 1]);
                    }
                }
            }
        }
    }
#pragma unroll
    for (int c2 = 0; c2 < 2; c2++) {
        int co = co0 + co_l + c2;
        float add = bias[co] + (MODE == 0 ? temb[b * 128 + co] : 0.f);
        int base = ((b * 128 + co) * 64 + h) * 64 + w0;
#pragma unroll
        for (int p = 0; p < 4; p++) {
            float2 v = unp2(acc2[c2][p]);
            float o0 = v.x + add, o1 = v.y + add;
            if (MODE == 1) { o0 += resid[base + 2 * p]; o1 += resid[base + 2 * p + 1]; }
            dst[base + 2 * p]     = o0;
            dst[base + 2 * p + 1] = o1;
        }
    }
}

// ------------------------- cond 1x1 projection (f32x2) -------------------------
__global__ void __launch_bounds__(256) cond1x1_k(const float* __restrict__ cond,
                                                 const float* __restrict__ wt,
                                                 const float* __restrict__ bias,
                                                 float* __restrict__ out) {
    __shared__ float ct[128 * 64];
    int uv0 = blockIdx.x * 64;
    int b = blockIdx.y, t = threadIdx.x;
    for (int i = 0; i < 32; i++) {
        int idx = t + i * 256;
        ct[idx] = cond[(b * 128 + (idx >> 6)) * 4096 + uv0 + (idx & 63)];
    }
    __syncthreads();
    int co = t & 127, uh = t >> 7;
    ull acc[16];
#pragma unroll
    for (int j = 0; j < 16; j++) acc[j] = 0ull;
    const float* wrow = wt + co * 128;
    for (int ci = 0; ci < 128; ci++) {
        ull wv = dup2(__ldg(wrow + ci));
        const ull* kr = (const ull*)&ct[ci * 64 + uh * 32];
#pragma unroll
        for (int j = 0; j < 16; j++) fma2(acc[j], wv, kr[j]);
    }
    float bv = bias[co];
    float* op = out + (b * 128 + co) * 4096 + uv0 + uh * 32;
#pragma unroll
    for (int j = 0; j < 16; j++) {
        float2 v = unp2(acc[j]);
        op[2 * j]     = v.x + bv;
        op[2 * j + 1] = v.y + bv;
    }
}

// ------------------------- transpose + scale: h1[b,c,h,w] -> h1T[b,w,h,c]/sqrt(C) ---------
__global__ void __launch_bounds__(256) transpose_k(const float* __restrict__ h1,
                                                   float* __restrict__ h1T) {
    __shared__ float sm[128 * 65];
    int h = blockIdx.x, b = blockIdx.y, t = threadIdx.x;
    const float* src = h1 + ((b * 128) * 64 + h) * 64;
    for (int i = 0; i < 32; i++) {
        int idx = t + i * 256;
        int c = idx >> 6, w = idx & 63;
        sm[c * 65 + w] = src[c * 4096 + w] * SCALE_Q;
    }
    __syncthreads();
    for (int i = 0; i < 32; i++) {
        int idx = t + i * 256;
        int w = idx >> 7, c = idx & 127;
        h1T[((b * 64 + w) * 64 + h) * 128 + c] = sm[c * 65 + w];
    }
}

// ------------------------- prefill: h2 = h1 + contrast_embed[aim[b]] -------------------------
__global__ void __launch_bounds__(256) prefill_k(const float* __restrict__ h1,
                                                 const float* __restrict__ emb,
                                                 const int* __restrict__ aim,
                                                 float* __restrict__ h2) {
    int i = blockIdx.x * 256 + threadIdx.x;   // float4 index
    int b = i >> 17, c = (i >> 10) & 127;
    float e = emb[aim[b] * 128 + c];
    float4 v = ((const float4*)h1)[i];
    v.x += e; v.y += e; v.z += e; v.w += e;
    ((float4*)h2)[i] = v;
}

// ------------------------- fused attention: per (b, w, uv-quarter) -------------------------
// As2[h][c2] ull s65; KsT[u][c2] ull s65; SsT[u][h] f32 s65 (holds raw exp after softmax pass)
// GEMM1: c-parity-packed S; softmax: exp (no max-sub; |S|<~6) + column sums -> rsm[u]
// GEMM2: O[h][c-pair] += dup(E[h][u]*rs[u]) * KsT[u][c2]
#define ATT_SMEM_BYTES (64 * 65 * 8 * 2 + 64 * 65 * 4 + (256 + 64) * 4)
__global__ void __launch_bounds__(256, 2) attn_k(const float* __restrict__ A,
                                                 const float* __restrict__ K,
                                                 float* __restrict__ h2) {
    extern __shared__ char smraw[];
    ull*   As2  = (ull*)smraw;
    ull*   KsT  = As2 + 64 * 65;
    float* SsT  = (float*)(KsT + 64 * 65);
    float* reds = SsT + 64 * 65;
    float* rsm  = reds + 256;

    int b = blockIdx.x, w = blockIdx.y, chunk = blockIdx.z;
    int t = threadIdx.x;

    // load A tile (64h x 128c), float alias of As2: index h*130 + c
    {
        float* Asf = (float*)As2;
        const float* Ab = A + ((b * 64 + w) * 64) * 128;
        for (int i = 0; i < 32; i++) {
            int idx = t + i * 256;
            Asf[(idx >> 7) * 130 + (idx & 127)] = Ab[idx];
        }
    }

    ull o2[4][4];
#pragma unroll
    for (int i = 0; i < 4; i++)
#pragma unroll
        for (int j = 0; j < 4; j++) o2[i][j] = 0ull;

    int q  = t & 15;        // h rows: q, q+16, q+32, q+48
    int ug = t >> 4;        // u-group / c2-group: 4*ug .. 4*ug+3
    int su = t & 63, qq = t >> 6;   // softmax mapping

    const float* Kb = K + b * 128 * 4096 + chunk * 1024;
    float* KsTf = (float*)KsT;

    // prefetch half of K tile 0 (c rows 0..63)
    float kreg[16];
#pragma unroll
    for (int i = 0; i < 16; i++) {
        int idx = t + i * 256;
        kreg[i] = Kb[(idx >> 6) * 4096 + (idx & 63)];
    }

    for (int tile = 0; tile < 16; tile++) {
        __syncthreads();                           // previous tile's readers done
        const float* Kt = Kb + tile * 64;
        // second half (c rows 64..127): LDG now, STS below
        float k2reg[16];
#pragma unroll
        for (int i = 0; i < 16; i++) {
            int idx = t + (i + 16) * 256;
            k2reg[i] = Kt[(idx >> 6) * 4096 + (idx & 63)];
        }
#pragma unroll
        for (int i = 0; i < 16; i++) {
            int idx = t + i * 256;
            KsTf[(idx & 63) * 130 + (idx >> 6)] = kreg[i];
        }
#pragma unroll
        for (int i = 0; i < 16; i++) {
            int idx = t + (i + 16) * 256;
            KsTf[(idx & 63) * 130 + (idx >> 6)] = k2reg[i];
        }
        __syncthreads();

        // ---- GEMM1: S = A K  (c-parity packed reduction) ----
        ull s2[4][4];
#pragma unroll
        for (int i = 0; i < 4; i++)
#pragma unroll
            for (int j = 0; j < 4; j++) s2[i][j] = 0ull;
#pragma unroll 2
        for (int c2 = 0; c2 < 64; c2++) {
            ull a2[4], k2[4];
#pragma unroll
            for (int i = 0; i < 4; i++) a2[i] = As2[(q + 16 * i) * 65 + c2];
#pragma unroll
            for (int j = 0; j < 4; j++) k2[j] = KsT[(4 * ug + j) * 65 + c2];
#pragma unroll
            for (int i = 0; i < 4; i++)
#pragma unroll
                for (int j = 0; j < 4; j++) fma2(s2[i][j], a2[i], k2[j]);
        }
#pragma unroll
        for (int i = 0; i < 4; i++)
#pragma unroll
            for (int j = 0; j < 4; j++) {
                float2 v = unp2(s2[i][j]);
                SsT[(4 * ug + j) * 65 + q + 16 * i] = v.x + v.y;
            }
        __syncthreads();

        // prefetch first half of next K tile (hidden behind softmax + GEMM2)
        if (tile < 15) {
            const float* Kn = Kb + (tile + 1) * 64;
#pragma unroll
            for (int i = 0; i < 16; i++) {
                int idx = t + i * 256;
                kreg[i] = Kn[(idx >> 6) * 4096 + (idx & 63)];
            }
        }

        // ---- exp (no max-sub) + column sums ----
        {
            float* Srow = SsT + su * 65 + qq * 16;
            float ps = 0.f;
#pragma unroll
            for (int hh = 0; hh < 16; hh++) {
                float e = __expf(Srow[hh]);
                Srow[hh] = e;
                ps += e;
            }
            reds[qq * 64 + su] = ps;
        }
        __syncthreads();
        if (t < 64)
            rsm[t] = 1.f / (reds[t] + reds[64 + t] + reds[128 + t] + reds[192 + t]);
        __syncthreads();

        // ---- GEMM2: O[h][c-pair] += dup(E[h][u]*rs[u]) * KsT[u][c2] ----
#pragma unroll 2
        for (int u = 0; u < 64; u++) {
            float rsv = rsm[u];
            ull pd[4], kt[4];
#pragma unroll
            for (int i = 0; i < 4; i++) pd[i] = dup2(SsT[u * 65 + q + 16 * i] * rsv);
#pragma unroll
            for (int j = 0; j < 4; j++) kt[j] = KsT[u * 65 + 4 * ug + j];
#pragma unroll
            for (int i = 0; i < 4; i++)
#pragma unroll
                for (int j = 0; j < 4; j++) fma2(o2[i][j], pd[i], kt[j]);
        }
    }

    // ---- epilogue: atomic accumulate into h2[b,c,h,w] ----
#pragma unroll
    for (int i = 0; i < 4; i++)
#pragma unroll
        for (int j = 0; j < 4; j++) {
            float2 v = unp2(o2[i][j]);
            int c0 = 2 * (4 * ug + j);
            int hh = q + 16 * i;
            atomicAdd(&h2[((b * 128 + c0)     * 64 + hh) * 64 + w], v.x);
            atomicAdd(&h2[((b * 128 + c0 + 1) * 64 + hh) * 64 + w], v.y);
        }
}

// ------------------------- launch -------------------------
extern "C" void kernel_launch(void* const* d_in, const int* in_sizes, int n_in,
                              void* d_out, int out_size) {
    const float* x    = (const float*)d_in[0];
    const float* tt   = (const float*)d_in[1];
    const int*   aim  = (const int*)d_in[2];
    const float* cond = (const float*)d_in[3];
    const float* g1s  = (const float*)d_in[4];
    const float* g1b  = (const float*)d_in[5];
    const float* c1w  = (const float*)d_in[6];
    const float* c1b  = (const float*)d_in[7];
    const float* mw   = (const float*)d_in[8];
    const float* mb   = (const float*)d_in[9];
    const float* cw   = (const float*)d_in[10];
    const float* cbi  = (const float*)d_in[11];
    const float* g2s  = (const float*)d_in[12];
    const float* g2b  = (const float*)d_in[13];
    const float* c2w  = (const float*)d_in[14];
    const float* c2b  = (const float*)d_in[15];
    const float* emb  = (const float*)d_in[16];
    float* out = (float*)d_out;

    float *act, *h1, *h1T, *cbuf, *h2, *temb, *mean, *rstd;
    cudaGetSymbolAddress((void**)&act,  g_act);
    cudaGetSymbolAddress((void**)&h1,   g_h1);
    cudaGetSymbolAddress((void**)&h1T,  g_h1T);
    cudaGetSymbolAddress((void**)&cbuf, g_cbuf);
    cudaGetSymbolAddress((void**)&h2,   g_h2);
    cudaGetSymbolAddress((void**)&temb, g_temb);
    cudaGetSymbolAddress((void**)&mean, g_mean);
    cudaGetSymbolAddress((void**)&rstd, g_rstd);

    cudaFuncSetAttribute(attn_k, cudaFuncAttributeMaxDynamicSharedMemorySize,
                         ATT_SMEM_BYTES);

    gn_stats_k<<<128, 256>>>(x, mean, rstd);
    gn_apply_k<<<2048, 256>>>(x, mean, rstd, g1s, g1b, act);
    temb_k<<<4, 128>>>(tt, mw, mb, temb);
    conv3x3_k<0><<<dim3(2, 64, 4), 256>>>(act, c1w, c1b, temb, nullptr, h1);
    cond1x1_k<<<dim3(64, 4), 256>>>(cond, cw, cbi, cbuf);
    transpose_k<<<dim3(64, 4), 256>>>(h1, h1T);
    prefill_k<<<2048, 256>>>(h1, emb, aim, h2);
    attn_k<<<dim3(4, 64, 4), 256, ATT_SMEM_BYTES>>>(h1T, cbuf, h2);
    gn_stats_k<<<128, 256>>>(h2, mean, rstd);
    gn_apply_k<<<2048, 256>>>(h2, mean, rstd, g2s, g2b, act);
    conv3x3_k<1><<<dim3(2, 64, 4), 256>>>(act, c2w, c2b, nullptr, x, out);
}

// round 10
// speedup vs baseline: 1.5169x; 1.5169x over previous
#include <cuda_runtime.h>
#include <cuda_bf16.h>
#include <math.h>
#include <stdint.h>

typedef unsigned long long ull;

#define NB 4
#define NC 128
#define NHW 4096
#define NG 32
#define NTD 512
#define SCALE_Q 0.088388347648318447f  /* 1/sqrt(128) */

// ------------------------- static scratch (no allocations) -------------------------
static __device__ float g_act [NB * NC * NHW];
static __device__ float g_h1  [NB * NC * NHW];
static __device__ float g_h1T [NB * NHW * NC];   // [b][w][h][c] * 1/sqrt(C)
static __device__ float g_cbuf[NB * NC * NHW];
static __device__ float g_h2  [NB * NC * NHW];
static __device__ float g_oT  [NB * NHW * NC];   // attn out [b][w][h][c]
static __device__ float g_temb[NB * NC];
static __device__ float g_mean[NB * NG];
static __device__ float g_rstd[NB * NG];
static __device__ __nv_bfloat16 g_khi [NB * NC * NHW];   // [b][c][u]
static __device__ __nv_bfloat16 g_klo [NB * NC * NHW];
static __device__ __nv_bfloat16 g_kthi[NB * NHW * NC];   // [b][u][c]
static __device__ __nv_bfloat16 g_ktlo[NB * NHW * NC];

// ------------------------- f32x2 helpers -------------------------
__device__ __forceinline__ void fma2(ull& d, ull a, ull b) {
    asm("fma.rn.f32x2 %0, %1, %2, %0;" : "+l"(d) : "l"(a), "l"(b));
}
__device__ __forceinline__ ull dup2(float x) {
    ull r;
    asm("mov.b64 %0, {%1, %2};" : "=l"(r) : "f"(x), "f"(x));
    return r;
}
__device__ __forceinline__ float2 unp2(ull v) {
    float2 r;
    asm("mov.b64 {%0, %1}, %2;" : "=f"(r.x), "=f"(r.y) : "l"(v));
    return r;
}
__device__ __forceinline__ float siluf(float x) { return x / (1.0f + __expf(-x)); }

__device__ __forceinline__ unsigned pack_bf16(float a, float b) {
    __nv_bfloat162 t = __floats2bfloat162_rn(a, b);
    return *reinterpret_cast<unsigned*>(&t);
}

// bf16 HMMA m16n8k16 (family-safe; NOT tcgen05)
__device__ __forceinline__ void mma16816(float* d, unsigned a0, unsigned a1,
                                         unsigned a2, unsigned a3,
                                         unsigned b0, unsigned b1) {
    asm volatile(
        "mma.sync.aligned.m16n8k16.row.col.f32.bf16.bf16.f32 "
        "{%0,%1,%2,%3}, {%4,%5,%6,%7}, {%8,%9}, {%0,%1,%2,%3};"
        : "+f"(d[0]), "+f"(d[1]), "+f"(d[2]), "+f"(d[3])
        : "r"(a0), "r"(a1), "r"(a2), "r"(a3), "r"(b0), "r"(b1));
}

// ------------------------- group-norm statistics -------------------------
__global__ void __launch_bounds__(256) gn_stats_k(const float* __restrict__ src,
                                                  float* __restrict__ mean,
                                                  float* __restrict__ rstd) {
    int bg = blockIdx.x;
    const float4* p = (const float4*)(src + bg * 16384);
    float s = 0.f, ss = 0.f;
    for (int i = threadIdx.x; i < 4096; i += 256) {
        float4 v = p[i];
        s  += v.x + v.y + v.z + v.w;
        ss += v.x * v.x + v.y * v.y + v.z * v.z + v.w * v.w;
    }
    for (int off = 16; off; off >>= 1) {
        s  += __shfl_down_sync(0xffffffffu, s,  off);
        ss += __shfl_down_sync(0xffffffffu, ss, off);
    }
    __shared__ float ws[8], wss[8];
    int wid = threadIdx.x >> 5, lane = threadIdx.x & 31;
    if (lane == 0) { ws[wid] = s; wss[wid] = ss; }
    __syncthreads();
    if (threadIdx.x == 0) {
        float ts = 0.f, tss = 0.f;
        for (int i = 0; i < 8; i++) { ts += ws[i]; tss += wss[i]; }
        float m = ts * (1.f / 16384.f);
        float var = tss * (1.f / 16384.f) - m * m;
        mean[bg] = m;
        rstd[bg] = rsqrtf(var + 1e-5f);
    }
}

// ------------------------- GN apply + SiLU -------------------------
__global__ void __launch_bounds__(256) gn_apply_k(const float* __restrict__ src,
                                                  const float* __restrict__ mean,
                                                  const float* __restrict__ rstd,
                                                  const float* __restrict__ sc,
                                                  const float* __restrict__ bi,
                                                  float* __restrict__ dst) {
    int i = blockIdx.x * 256 + threadIdx.x;
    int c  = (i >> 10) & 127;
    int bg = (i >> 17) * 32 + (c >> 2);
    float m = mean[bg], r = rstd[bg];
    float a = r * sc[c];
    float b = bi[c] - m * a;
    float4 v = ((const float4*)src)[i];
    v.x = siluf(v.x * a + b);
    v.y = siluf(v.y * a + b);
    v.z = siluf(v.z * a + b);
    v.w = siluf(v.w * a + b);
    ((float4*)dst)[i] = v;
}

// ------------------------- time embedding -------------------------
__global__ void __launch_bounds__(128) temb_k(const float* __restrict__ t,
                                              const float* __restrict__ mw,
                                              const float* __restrict__ mb,
                                              float* __restrict__ temb) {
    __shared__ float st[NTD];
    int b = blockIdx.x, tid = threadIdx.x;
    for (int k = tid; k < NTD; k += 128) st[k] = siluf(t[b * NTD + k]);
    __syncthreads();
    float acc = mb[tid];
    const float* wr = mw + tid * NTD;
#pragma unroll 8
    for (int k = 0; k < NTD; k++) acc += st[k] * wr[k];
    temb[b * NC + tid] = acc;
}

// ------------------------- 3x3 conv (R8 version) -------------------------
template <int MODE>
__global__ void __launch_bounds__(256) conv3x3_k(const float* __restrict__ src,
                                                 const float* __restrict__ wgt,
                                                 const float* __restrict__ bias,
                                                 const float* __restrict__ temb,
                                                 const float* __restrict__ resid,
                                                 float* __restrict__ dst) {
    __shared__ __align__(16) float in_s[8 * 3 * 66];
    __shared__ __align__(16) float in_o[8 * 3 * 66];
    __shared__ float wt_s[64 * 73];
    int co0 = blockIdx.x * 64;
    int h   = blockIdx.y;
    int b   = blockIdx.z;
    int t   = threadIdx.x;
    int co_l = (t & 31) * 2;
    int w0   = (t >> 5) * 8;
    int wco = t >> 2;
    int wr0 = 18 * (t & 3);

    ull acc2[2][4];
#pragma unroll
    for (int c2 = 0; c2 < 2; c2++)
#pragma unroll
        for (int p = 0; p < 4; p++) acc2[c2][p] = 0ull;

    float wreg[18];
    float ireg[7];
    {
        const float* wp = wgt + (co0 + wco) * 1152 + wr0;
#pragma unroll
        for (int j = 0; j < 18; j++) wreg[j] = wp[j];
#pragma unroll
        for (int j = 0; j < 7; j++) {
            int idx = t + j * 256;
            float v = 0.f;
            if (idx < 1584) {
                int ci = idx / 198, r = idx % 198, kh = r / 66, wpp = r % 66;
                int hh = h - 1 + kh, wc = wpp - 1;
                if (hh >= 0 && hh < 64 && wc >= 0 && wc < 64)
                    v = src[((b * 128 + ci) * 64 + hh) * 64 + wc];
            }
            ireg[j] = v;
        }
    }

    for (int chunk = 0; chunk < 16; chunk++) {
        __syncthreads();
#pragma unroll
        for (int j = 0; j < 18; j++) wt_s[wco * 73 + wr0 + j] = wreg[j];
#pragma unroll
        for (int j = 0; j < 7; j++) {
            int idx = t + j * 256;
            if (idx < 1584) {
                in_s[idx] = ireg[j];
                int wpp = idx % 66;
                if (wpp > 0) in_o[idx - 1] = ireg[j];
            }
        }
        __syncthreads();
        if (chunk < 15) {
            int ci0n = (chunk + 1) * 8;
            const float* wp = wgt + (co0 + wco) * 1152 + ci0n * 9 + wr0;
#pragma unroll
            for (int j = 0; j < 18; j++) wreg[j] = wp[j];
#pragma unroll
            for (int j = 0; j < 7; j++) {
                int idx = t + j * 256;
                float v = 0.f;
                if (idx < 1584) {
                    int ci = idx / 198, r = idx % 198, kh = r / 66, wpp = r % 66;
                    int hh = h - 1 + kh, wc = wpp - 1;
                    if (hh >= 0 && hh < 64 && wc >= 0 && wc < 64)
                        v = src[((b * 128 + ci0n + ci) * 64 + hh) * 64 + wc];
                }
                ireg[j] = v;
            }
        }
#pragma unroll
        for (int ci = 0; ci < 8; ci++) {
#pragma unroll
            for (int kh = 0; kh < 3; kh++) {
                const ull* ep0 = (const ull*)&in_s[ci * 198 + kh * 66 + w0];
                const ull* ep1 = (const ull*)&in_o[ci * 198 + kh * 66 + w0];
                ull e0[5], e1[4];
#pragma unroll
                for (int p = 0; p < 5; p++) e0[p] = ep0[p];
#pragma unroll
                for (int p = 0; p < 4; p++) e1[p] = ep1[p];
#pragma unroll
                for (int c2 = 0; c2 < 2; c2++) {
                    const float* wr = &wt_s[(co_l + c2) * 73 + ci * 9 + kh * 3];
                    ull wad = dup2(wr[0]), wbd = dup2(wr[1]), wcd = dup2(wr[2]);
#pragma unroll
                    for (int p = 0; p < 4; p++) {
                        fma2(acc2[c2][p], wad, e0[p]);
                        fma2(acc2[c2][p], wbd, e1[p]);
                        fma2(acc2[c2][p], wcd, e0[p + 1]);
                    }
                }
            }
        }
    }
#pragma unroll
    for (int c2 = 0; c2 < 2; c2++) {
        int co = co0 + co_l + c2;
        float add = bias[co] + (MODE == 0 ? temb[b * 128 + co] : 0.f);
        int base = ((b * 128 + co) * 64 + h) * 64 + w0;
#pragma unroll
        for (int p = 0; p < 4; p++) {
            float2 v = unp2(acc2[c2][p]);
            float o0 = v.x + add, o1 = v.y + add;
            if (MODE == 1) { o0 += resid[base + 2 * p]; o1 += resid[base + 2 * p + 1]; }
            dst[base + 2 * p]     = o0;
            dst[base + 2 * p + 1] = o1;
        }
    }
}

// ------------------------- cond 1x1 projection -------------------------
__global__ void __launch_bounds__(256) cond1x1_k(const float* __restrict__ cond,
                                                 const float* __restrict__ wt,
                                                 const float* __restrict__ bias,
                                                 float* __restrict__ out) {
    __shared__ float ct[128 * 64];
    int uv0 = blockIdx.x * 64;
    int b = blockIdx.y, t = threadIdx.x;
    for (int i = 0; i < 32; i++) {
        int idx = t + i * 256;
        ct[idx] = cond[(b * 128 + (idx >> 6)) * 4096 + uv0 + (idx & 63)];
    }
    __syncthreads();
    int co = t & 127, uh = t >> 7;
    ull acc[16];
#pragma unroll
    for (int j = 0; j < 16; j++) acc[j] = 0ull;
    const float* wrow = wt + co * 128;
    for (int ci = 0; ci < 128; ci++) {
        ull wv = dup2(__ldg(wrow + ci));
        const ull* kr = (const ull*)&ct[ci * 64 + uh * 32];
#pragma unroll
        for (int j = 0; j < 16; j++) fma2(acc[j], wv, kr[j]);
    }
    float bv = bias[co];
    float* op = out + (b * 128 + co) * 4096 + uv0 + uh * 32;
#pragma unroll
    for (int j = 0; j < 16; j++) {
        float2 v = unp2(acc[j]);
        op[2 * j]     = v.x + bv;
        op[2 * j + 1] = v.y + bv;
    }
}

// ------------------------- K split: fp32 -> bf16 hi/lo, both orientations -------------------------
__global__ void __launch_bounds__(256) ksplit_k(const float* __restrict__ cbuf,
                                                __nv_bfloat16* __restrict__ khi,
                                                __nv_bfloat16* __restrict__ klo,
                                                __nv_bfloat16* __restrict__ kthi,
                                                __nv_bfloat16* __restrict__ ktlo) {
    __shared__ float ct[128 * 65];
    int u0 = blockIdx.x * 64, b = blockIdx.y, t = threadIdx.x;
    for (int i = 0; i < 32; i++) {
        int idx = t + i * 256;
        int c = idx >> 6, u = idx & 63;
        ct[c * 65 + u] = cbuf[(b * 128 + c) * 4096 + u0 + u];
    }
    __syncthreads();
    {
        int c = t >> 1, uh = (t & 1) * 32;
        unsigned hi[16], lo[16];
#pragma unroll
        for (int j = 0; j < 16; j++) {
            float f0 = ct[c * 65 + uh + 2 * j], f1 = ct[c * 65 + uh + 2 * j + 1];
            float h0 = __bfloat162float(__float2bfloat16(f0));
            float h1 = __bfloat162float(__float2bfloat16(f1));
            hi[j] = pack_bf16(h0, h1);
            lo[j] = pack_bf16(f0 - h0, f1 - h1);
        }
        uint4* dh = (uint4*)(khi + (size_t)(b * 128 + c) * 4096 + u0 + uh);
        uint4* dl = (uint4*)(klo + (size_t)(b * 128 + c) * 4096 + u0 + uh);
#pragma unroll
        for (int q = 0; q < 4; q++) {
            dh[q] = make_uint4(hi[4*q], hi[4*q+1], hi[4*q+2], hi[4*q+3]);
            dl[q] = make_uint4(lo[4*q], lo[4*q+1], lo[4*q+2], lo[4*q+3]);
        }
    }
    {
        int u = t & 63, ch = (t >> 6) * 32;
        unsigned hi[16], lo[16];
#pragma unroll
        for (int j = 0; j < 16; j++) {
            float f0 = ct[(ch + 2 * j) * 65 + u], f1 = ct[(ch + 2 * j + 1) * 65 + u];
            float h0 = __bfloat162float(__float2bfloat16(f0));
            float h1 = __bfloat162float(__float2bfloat16(f1));
            hi[j] = pack_bf16(h0, h1);
            lo[j] = pack_bf16(f0 - h0, f1 - h1);
        }
        uint4* dh = (uint4*)(kthi + (size_t)(b * 4096 + u0 + u) * 128 + ch);
        uint4* dl = (uint4*)(ktlo + (size_t)(b * 4096 + u0 + u) * 128 + ch);
#pragma unroll
        for (int q = 0; q < 4; q++) {
            dh[q] = make_uint4(hi[4*q], hi[4*q+1], hi[4*q+2], hi[4*q+3]);
            dl[q] = make_uint4(lo[4*q], lo[4*q+1], lo[4*q+2], lo[4*q+3]);
        }
    }
}

// ------------------------- transpose + scale: h1 -> h1T -------------------------
__global__ void __launch_bounds__(256) transpose_k(const float* __restrict__ h1,
                                                   float* __restrict__ h1T) {
    __shared__ float sm[128 * 65];
    int h = blockIdx.x, b = blockIdx.y, t = threadIdx.x;
    const float* src = h1 + ((b * 128) * 64 + h) * 64;
    for (int i = 0; i < 32; i++) {
        int idx = t + i * 256;
        int c = idx >> 6, w = idx & 63;
        sm[c * 65 + w] = src[c * 4096 + w] * SCALE_Q;
    }
    __syncthreads();
    for (int i = 0; i < 32; i++) {
        int idx = t + i * 256;
        int w = idx >> 7, c = idx & 127;
        h1T[((b * 64 + w) * 64 + h) * 128 + c] = sm[c * 65 + w];
    }
}

// ------------------------- prefill: h2 = h1 + contrast_embed[aim[b]] -------------------------
__global__ void __launch_bounds__(256) prefill_k(const float* __restrict__ h1,
                                                 const float* __restrict__ emb,
                                                 const int* __restrict__ aim,
                                                 float* __restrict__ h2) {
    int i = blockIdx.x * 256 + threadIdx.x;
    int b = i >> 17, c = (i >> 10) & 127;
    float e = emb[aim[b] * 128 + c];
    float4 v = ((const float4*)h1)[i];
    v.x += e; v.y += e; v.z += e; v.w += e;
    ((float4*)h2)[i] = v;
}

// ------------------------- transadd: h2[b][c][h][w] += oT[b][w][h][c] -------------------------
__global__ void __launch_bounds__(256) transadd_k(const float* __restrict__ oT,
                                                  float* __restrict__ h2) {
    __shared__ float sm[64 * 129];
    int h = blockIdx.x, b = blockIdx.y, t = threadIdx.x;
    for (int i = 0; i < 32; i++) {
        int idx = t + i * 256;
        int w = idx >> 7, c = idx & 127;
        sm[w * 129 + c] = oT[((b * 64 + w) * 64 + h) * 128 + c];
    }
    __syncthreads();
    for (int i = 0; i < 32; i++) {
        int idx = t + i * 256;
        int c = idx >> 6, w = idx & 63;
        h2[((b * 128 + c) * 64 + h) * 64 + w] += sm[w * 129 + c];
    }
}

// ------------------------- mma.sync attention: block per (b, w-pair) -------------------------
// SMEM (u32-unit row strides): A hi/lo [128m][68], KT hi/lo [64u][68],
// Kc hi/lo [128c][36], SsT f32 [64u][129], P hi/lo [128m][36], reds[4][64], rsm[2][64]
#define OFF_AHI  0
#define OFF_ALO  (OFF_AHI + 128 * 68 * 4)
#define OFF_KTHI (OFF_ALO + 128 * 68 * 4)
#define OFF_KTLO (OFF_KTHI + 64 * 68 * 4)
#define OFF_KCHI (OFF_KTLO + 64 * 68 * 4)
#define OFF_KCLO (OFF_KCHI + 128 * 36 * 4)
#define OFF_SST  (OFF_KCLO + 128 * 36 * 4)
#define OFF_REDS (OFF_SST + 64 * 129 * 4)
#define OFF_RSM  (OFF_REDS + 256 * 4)
#define OFF_PHI  (OFF_RSM + 128 * 4)
#define OFF_PLO  (OFF_PHI + 128 * 36 * 4)
#define ATTN_SMEM (OFF_PLO + 128 * 36 * 4)

__global__ void __launch_bounds__(256, 1) attn_mma_k(const float* __restrict__ h1T,
        const __nv_bfloat16* __restrict__ khi, const __nv_bfloat16* __restrict__ klo,
        const __nv_bfloat16* __restrict__ kthi, const __nv_bfloat16* __restrict__ ktlo,
        float* __restrict__ oT) {
    extern __shared__ __align__(16) char sm[];
    unsigned* Ahi  = (unsigned*)(sm + OFF_AHI);
    unsigned* Alo  = (unsigned*)(sm + OFF_ALO);
    unsigned* KThi = (unsigned*)(sm + OFF_KTHI);
    unsigned* KTlo = (unsigned*)(sm + OFF_KTLO);
    unsigned* Kchi = (unsigned*)(sm + OFF_KCHI);
    unsigned* Kclo = (unsigned*)(sm + OFF_KCLO);
    float*    SsT  = (float*)(sm + OFF_SST);
    float*    reds = (float*)(sm + OFF_REDS);
    float*    rsm  = (float*)(sm + OFF_RSM);
    unsigned* Phi  = (unsigned*)(sm + OFF_PHI);
    unsigned* Plo  = (unsigned*)(sm + OFF_PLO);

    int t = threadIdx.x, lane = t & 31, wid = t >> 5;
    int wp = blockIdx.x, b = blockIdx.y;
    int g = lane >> 2, tq = lane & 3;
    int mrow = wid * 16;

    // ---- A split -> smem (once). Row m = w_local*64 + h ----
    {
        int m = t >> 1, ch = (t & 1) * 64;
        const float* ar = h1T + (size_t)((b * 64 + 2 * wp + (m >> 6)) * 64 + (m & 63)) * 128 + ch;
        unsigned* dh = Ahi + m * 68 + (ch >> 1);
        unsigned* dl = Alo + m * 68 + (ch >> 1);
#pragma unroll
        for (int j = 0; j < 32; j++) {
            float f0 = ar[2 * j], f1 = ar[2 * j + 1];
            float h0 = __bfloat162float(__float2bfloat16(f0));
            float h1 = __bfloat162float(__float2bfloat16(f1));
            dh[j] = pack_bf16(h0, h1);
            dl[j] = pack_bf16(f0 - h0, f1 - h1);
        }
    }

    float o[16][4];
#pragma unroll
    for (int n = 0; n < 16; n++)
#pragma unroll
        for (int k = 0; k < 4; k++) o[n][k] = 0.f;

    for (int tile = 0; tile < 64; tile++) {
        int u0 = tile * 64;
        __syncthreads();   // previous tile's consumers done
        // ---- K tile copies (16B chunks, coalesced, conflict-padded dest) ----
#pragma unroll
        for (int i = 0; i < 4; i++) {
            int cidx = t + i * 256;
            {   // KT: [u][c] 64x128 bf16, 16 chunks/row
                int u = cidx >> 4, q = cidx & 15;
                const uint4* sh = (const uint4*)(kthi + (size_t)(b * 4096 + u0 + u) * 128 + q * 8);
                const uint4* sl = (const uint4*)(ktlo + (size_t)(b * 4096 + u0 + u) * 128 + q * 8);
                *(uint4*)(KThi + u * 68 + q * 4) = *sh;
                *(uint4*)(KTlo + u * 68 + q * 4) = *sl;
            }
            {   // Kc: [c][u] 128x64 bf16, 8 chunks/row
                int c = cidx >> 3, q = cidx & 7;
                const uint4* sh = (const uint4*)(khi + (size_t)(b * 128 + c) * 4096 + u0 + q * 8);
                const uint4* sl = (const uint4*)(klo + (size_t)(b * 128 + c) * 4096 + u0 + q * 8);
                *(uint4*)(Kchi + c * 36 + q * 4) = *sh;
                *(uint4*)(Kclo + c * 36 + q * 4) = *sl;
            }
        }
        __syncthreads();

        // ---- GEMM1: S(128m x 64u) = A(128x128c) * K^T; warp = m16 x 64u ----
        float s[8][4];
#pragma unroll
        for (int n = 0; n < 8; n++)
#pragma unroll
            for (int k = 0; k < 4; k++) s[n][k] = 0.f;
#pragma unroll
        for (int ks = 0; ks < 8; ks++) {
            int r0 = (mrow + g) * 68 + 8 * ks + tq;
            int r1 = (mrow + g + 8) * 68 + 8 * ks + tq;
            unsigned ah0 = Ahi[r0], ah1 = Ahi[r1], ah2 = Ahi[r0 + 4], ah3 = Ahi[r1 + 4];
            unsigned al0 = Alo[r0], al1 = Alo[r1], al2 = Alo[r0 + 4], al3 = Alo[r1 + 4];
#pragma unroll
            for (int n = 0; n < 8; n++) {
                int bi = (8 * n + g) * 68 + 8 * ks + tq;
                unsigned bh0 = KThi[bi], bh1 = KThi[bi + 4];
                unsigned bl0 = KTlo[bi], bl1 = KTlo[bi + 4];
                mma16816(s[n], ah0, ah1, ah2, ah3, bh0, bh1);
                mma16816(s[n], ah0, ah1, ah2, ah3, bl0, bl1);
                mma16816(s[n], al0, al1, al2, al3, bh0, bh1);
            }
        }
        // ---- scatter S -> SsT[u][m] ----
#pragma unroll
        for (int n = 0; n < 8; n++) {
            int ub = 8 * n + 2 * tq;
            SsT[ub * 129 + mrow + g]           = s[n][0];
            SsT[(ub + 1) * 129 + mrow + g]     = s[n][1];
            SsT[ub * 129 + mrow + g + 8]       = s[n][2];
            SsT[(ub + 1) * 129 + mrow + g + 8] = s[n][3];
        }
        __syncthreads();

        // ---- exp + partial column sums (per w-half) ----
        {
            int u = t & 63, qq = t >> 6;
            float* col = SsT + u * 129 + qq * 32;
            float ps = 0.f;
#pragma unroll
            for (int j = 0; j < 32; j++) {
                float e = __expf(col[j]);
                col[j] = e;
                ps += e;
            }
            reds[qq * 64 + u] = ps;
        }
        __syncthreads();
        if (t < 128) {
            int half = t >> 6, u = t & 63;
            rsm[half * 64 + u] = 1.f / (reds[2 * half * 64 + u] + reds[(2 * half + 1) * 64 + u]);
        }
        __syncthreads();

        // ---- P = E * rs, split -> P smem [m][u] ----
        {
            int m = t >> 1, uh = (t & 1) * 32, half = m >> 6;
            const float* rp = rsm + half * 64;
            unsigned* ph = Phi + m * 36 + (uh >> 1);
            unsigned* pl = Plo + m * 36 + (uh >> 1);
#pragma unroll
            for (int j = 0; j < 16; j++) {
                int u = uh + 2 * j;
                float p0 = SsT[u * 129 + m] * rp[u];
                float p1 = SsT[(u + 1) * 129 + m] * rp[u + 1];
                float h0 = __bfloat162float(__float2bfloat16(p0));
                float h1 = __bfloat162float(__float2bfloat16(p1));
                ph[j] = pack_bf16(h0, h1);
                pl[j] = pack_bf16(p0 - h0, p1 - h1);
            }
        }
        __syncthreads();

        // ---- GEMM2: O(128m x 128c) += P(128x64u) * K; warp = m16 x 128c ----
#pragma unroll
        for (int ks = 0; ks < 4; ks++) {
            int r0 = (mrow + g) * 36 + 8 * ks + tq;
            int r1 = (mrow + g + 8) * 36 + 8 * ks + tq;
            unsigned ph0 = Phi[r0], ph1 = Phi[r1], ph2 = Phi[r0 + 4], ph3 = Phi[r1 + 4];
            unsigned pl0 = Plo[r0], pl1 = Plo[r1], pl2 = Plo[r0 + 4], pl3 = Plo[r1 + 4];
#pragma unroll
            for (int n = 0; n < 16; n++) {
                int bi = (8 * n + g) * 36 + 8 * ks + tq;
                unsigned bh0 = Kchi[bi], bh1 = Kchi[bi + 4];
                unsigned bl0 = Kclo[bi], bl1 = Kclo[bi + 4];
                mma16816(o[n], ph0, ph1, ph2, ph3, bh0, bh1);
                mma16816(o[n], ph0, ph1, ph2, ph3, bl0, bl1);
                mma16816(o[n], pl0, pl1, pl2, pl3, bh0, bh1);
            }
        }
    }

    // ---- epilogue: O -> oT[b][w][h][c] ----
    {
        size_t base = (size_t)(b * 64 + 2 * wp + (mrow >> 6)) * 64;
        int hrow = (mrow & 63) + g;
        float* r0 = oT + (base + hrow) * 128;
        float* r1 = oT + (base + hrow + 8) * 128;
#pragma unroll
        for (int n = 0; n < 16; n++) {
            *(float2*)(r0 + 8 * n + 2 * tq) = make_float2(o[n][0], o[n][1]);
            *(float2*)(r1 + 8 * n + 2 * tq) = make_float2(o[n][2], o[n][3]);
        }
    }
}

// ------------------------- launch -------------------------
extern "C" void kernel_launch(void* const* d_in, const int* in_sizes, int n_in,
                              void* d_out, int out_size) {
    const float* x    = (const float*)d_in[0];
    const float* tt   = (const float*)d_in[1];
    const int*   aim  = (const int*)d_in[2];
    const float* cond = (const float*)d_in[3];
    const float* g1s  = (const float*)d_in[4];
    const float* g1b  = (const float*)d_in[5];
    const float* c1w  = (const float*)d_in[6];
    const float* c1b  = (const float*)d_in[7];
    const float* mw   = (const float*)d_in[8];
    const float* mb   = (const float*)d_in[9];
    const float* cw   = (const float*)d_in[10];
    const float* cbi  = (const float*)d_in[11];
    const float* g2s  = (const float*)d_in[12];
    const float* g2b  = (const float*)d_in[13];
    const float* c2w  = (const float*)d_in[14];
    const float* c2b  = (const float*)d_in[15];
    const float* emb  = (const float*)d_in[16];
    float* out = (float*)d_out;

    float *act, *h1, *h1T, *cbuf, *h2, *oT, *temb, *mean, *rstd;
    __nv_bfloat16 *khi, *klo, *kthi, *ktlo;
    cudaGetSymbolAddress((void**)&act,  g_act);
    cudaGetSymbolAddress((void**)&h1,   g_h1);
    cudaGetSymbolAddress((void**)&h1T,  g_h1T);
    cudaGetSymbolAddress((void**)&cbuf, g_cbuf);
    cudaGetSymbolAddress((void**)&h2,   g_h2);
    cudaGetSymbolAddress((void**)&oT,   g_oT);
    cudaGetSymbolAddress((void**)&temb, g_temb);
    cudaGetSymbolAddress((void**)&mean, g_mean);
    cudaGetSymbolAddress((void**)&rstd, g_rstd);
    cudaGetSymbolAddress((void**)&khi,  g_khi);
    cudaGetSymbolAddress((void**)&klo,  g_klo);
    cudaGetSymbolAddress((void**)&kthi, g_kthi);
    cudaGetSymbolAddress((void**)&ktlo, g_ktlo);

    cudaFuncSetAttribute(attn_mma_k, cudaFuncAttributeMaxDynamicSharedMemorySize,
                         ATTN_SMEM);

    gn_stats_k<<<128, 256>>>(x, mean, rstd);
    gn_apply_k<<<2048, 256>>>(x, mean, rstd, g1s, g1b, act);
    temb_k<<<4, 128>>>(tt, mw, mb, temb);
    conv3x3_k<0><<<dim3(2, 64, 4), 256>>>(act, c1w, c1b, temb, nullptr, h1);
    cond1x1_k<<<dim3(64, 4), 256>>>(cond, cw, cbi, cbuf);
    ksplit_k<<<dim3(64, 4), 256>>>(cbuf, khi, klo, kthi, ktlo);
    transpose_k<<<dim3(64, 4), 256>>>(h1, h1T);
    prefill_k<<<2048, 256>>>(h1, emb, aim, h2);
    attn_mma_k<<<dim3(32, 4), 256, ATTN_SMEM>>>(h1T, khi, klo, kthi, ktlo, oT);
    transadd_k<<<dim3(64, 4), 256>>>(oT, h2);
    gn_stats_k<<<128, 256>>>(h2, mean, rstd);
    gn_apply_k<<<2048, 256>>>(h2, mean, rstd, g2s, g2b, act);
    conv3x3_k<1><<<dim3(2, 64, 4), 256>>>(act, c2w, c2b, nullptr, x, out);
}

// round 12
// speedup vs baseline: 2.0895x; 1.3775x over previous
#include <cuda_runtime.h>
#include <cuda_bf16.h>
#include <math.h>
#include <stdint.h>

typedef unsigned long long ull;

#define NB 4
#define NC 128
#define NHW 4096
#define NG 32
#define NTD 512
#define SCALE_Q 0.088388347648318447f  /* 1/sqrt(128) */

// ------------------------- static scratch (no allocations) -------------------------
static __device__ float g_act [NB * NC * NHW];
static __device__ float g_h1  [NB * NC * NHW];
static __device__ float g_h1T [NB * NHW * NC];   // [b][w][h][c] * 1/sqrt(C)
static __device__ float g_cbuf[NB * NC * NHW];
static __device__ float g_h2  [NB * NC * NHW];
static __device__ float g_oT  [NB * NHW * NC];   // attn out [b][w][h][c]
static __device__ float g_temb[NB * NC];
static __device__ float g_mean[NB * NG];
static __device__ float g_rstd[NB * NG];
static __device__ __nv_bfloat16 g_khi [NB * NC * NHW];   // [b][c][u]
static __device__ __nv_bfloat16 g_klo [NB * NC * NHW];
static __device__ __nv_bfloat16 g_kthi[NB * NHW * NC];   // [b][u][c]
static __device__ __nv_bfloat16 g_ktlo[NB * NHW * NC];
static __device__ __nv_bfloat16 g_athi[NB * NHW * NC];   // act transposed [b][h][w][c]
static __device__ __nv_bfloat16 g_atlo[NB * NHW * NC];
static __device__ __nv_bfloat16 g_whi [3 * 128 * 384];   // weights [kh][co][kw*128+ci]
static __device__ __nv_bfloat16 g_wlo [3 * 128 * 384];

// ------------------------- helpers -------------------------
__device__ __forceinline__ void fma2(ull& d, ull a, ull b) {
    asm("fma.rn.f32x2 %0, %1, %2, %0;" : "+l"(d) : "l"(a), "l"(b));
}
__device__ __forceinline__ ull dup2(float x) {
    ull r;
    asm("mov.b64 %0, {%1, %2};" : "=l"(r) : "f"(x), "f"(x));
    return r;
}
__device__ __forceinline__ float2 unp2(ull v) {
    float2 r;
    asm("mov.b64 {%0, %1}, %2;" : "=f"(r.x), "=f"(r.y) : "l"(v));
    return r;
}
__device__ __forceinline__ float siluf(float x) { return x / (1.0f + __expf(-x)); }

__device__ __forceinline__ unsigned pack_bf16(float a, float b) {
    __nv_bfloat162 t = __floats2bfloat162_rn(a, b);
    return *reinterpret_cast<unsigned*>(&t);
}

// bf16 HMMA m16n8k16 (family-safe PTX)
__device__ __forceinline__ void mma16816(float* d, unsigned a0, unsigned a1,
                                         unsigned a2, unsigned a3,
                                         unsigned b0, unsigned b1) {
    asm volatile(
        "mma.sync.aligned.m16n8k16.row.col.f32.bf16.bf16.f32 "
        "{%0,%1,%2,%3}, {%4,%5,%6,%7}, {%8,%9}, {%0,%1,%2,%3};"
        : "+f"(d[0]), "+f"(d[1]), "+f"(d[2]), "+f"(d[3])
        : "r"(a0), "r"(a1), "r"(a2), "r"(a3), "r"(b0), "r"(b1));
}

// ------------------------- group-norm statistics -------------------------
__global__ void __launch_bounds__(256) gn_stats_k(const float* __restrict__ src,
                                                  float* __restrict__ mean,
                                                  float* __restrict__ rstd) {
    int bg = blockIdx.x;
    const float4* p = (const float4*)(src + bg * 16384);
    float s = 0.f, ss = 0.f;
    for (int i = threadIdx.x; i < 4096; i += 256) {
        float4 v = p[i];
        s  += v.x + v.y + v.z + v.w;
        ss += v.x * v.x + v.y * v.y + v.z * v.z + v.w * v.w;
    }
    for (int off = 16; off; off >>= 1) {
        s  += __shfl_down_sync(0xffffffffu, s,  off);
        ss += __shfl_down_sync(0xffffffffu, ss, off);
    }
    __shared__ float ws[8], wss[8];
    int wid = threadIdx.x >> 5, lane = threadIdx.x & 31;
    if (lane == 0) { ws[wid] = s; wss[wid] = ss; }
    __syncthreads();
    if (threadIdx.x == 0) {
        float ts = 0.f, tss = 0.f;
        for (int i = 0; i < 8; i++) { ts += ws[i]; tss += wss[i]; }
        float m = ts * (1.f / 16384.f);
        float var = tss * (1.f / 16384.f) - m * m;
        mean[bg] = m;
        rstd[bg] = rsqrtf(var + 1e-5f);
    }
}

// ------------------------- GN apply + SiLU -------------------------
__global__ void __launch_bounds__(256) gn_apply_k(const float* __restrict__ src,
                                                  const float* __restrict__ mean,
                                                  const float* __restrict__ rstd,
                                                  const float* __restrict__ sc,
                                                  const float* __restrict__ bi,
                                                  float* __restrict__ dst) {
    int i = blockIdx.x * 256 + threadIdx.x;
    int c  = (i >> 10) & 127;
    int bg = (i >> 17) * 32 + (c >> 2);
    float m = mean[bg], r = rstd[bg];
    float a = r * sc[c];
    float b = bi[c] - m * a;
    float4 v = ((const float4*)src)[i];
    v.x = siluf(v.x * a + b);
    v.y = siluf(v.y * a + b);
    v.z = siluf(v.z * a + b);
    v.w = siluf(v.w * a + b);
    ((float4*)dst)[i] = v;
}

// ------------------------- time embedding -------------------------
__global__ void __launch_bounds__(128) temb_k(const float* __restrict__ t,
                                              const float* __restrict__ mw,
                                              const float* __restrict__ mb,
                                              float* __restrict__ temb) {
    __shared__ float st[NTD];
    int b = blockIdx.x, tid = threadIdx.x;
    for (int k = tid; k < NTD; k += 128) st[k] = siluf(t[b * NTD + k]);
    __syncthreads();
    float acc = mb[tid];
    const float* wr = mw + tid * NTD;
#pragma unroll 8
    for (int k = 0; k < NTD; k++) acc += st[k] * wr[k];
    temb[b * NC + tid] = acc;
}

// ------------------------- weight reorder + split: [co][ci][3][3] -> [kh][co][kw*128+ci] ---
__global__ void __launch_bounds__(256) wsplit_k(const float* __restrict__ wgt,
                                                __nv_bfloat16* __restrict__ whi,
                                                __nv_bfloat16* __restrict__ wlo) {
    int o = blockIdx.x * 256 + threadIdx.x;          // 147456 outputs
    int kh = o / 49152, r = o % 49152;
    int co = r / 384,  r2 = r % 384;
    int kw = r2 >> 7,  ci = r2 & 127;
    float v = wgt[((co * 128 + ci) * 3 + kh) * 3 + kw];
    float hv = __bfloat162float(__float2bfloat16(v));
    whi[o] = __float2bfloat16(hv);
    wlo[o] = __float2bfloat16(v - hv);
}

// ------------------------- act transpose + split: [b][c][h][w] -> bf16 [b][h][w][c] -------
__global__ void __launch_bounds__(256) actsplit_k(const float* __restrict__ act,
                                                  __nv_bfloat16* __restrict__ athi,
                                                  __nv_bfloat16* __restrict__ atlo) {
    __shared__ float smt[128 * 65];
    int h = blockIdx.x, b = blockIdx.y, t = threadIdx.x;
    for (int i = 0; i < 32; i++) {
        int idx = t + i * 256;
        int c = idx >> 6, w = idx & 63;
        smt[c * 65 + w] = act[(b * 128 + c) * 4096 + h * 64 + w];
    }
    __syncthreads();
    unsigned* oh = (unsigned*)(athi + (size_t)(b * 64 + h) * 64 * 128);
    unsigned* ol = (unsigned*)(atlo + (size_t)(b * 64 + h) * 64 * 128);
    for (int i = 0; i < 16; i++) {
        int idx = t + i * 256;                        // 4096 u32
        int w = idx >> 6, cp = idx & 63;
        float f0 = smt[(2 * cp) * 65 + w], f1 = smt[(2 * cp + 1) * 65 + w];
        float h0 = __bfloat162float(__float2bfloat16(f0));
        float h1 = __bfloat162float(__float2bfloat16(f1));
        oh[w * 64 + cp] = pack_bf16(h0, h1);
        ol[w * 64 + cp] = pack_bf16(f0 - h0, f1 - h1);
    }
}

// ------------------------- tensor-core 3x3 conv: block per (b,h) -------------------------
// W (A operand, row-major [co][k]) / X (B operand, col-major [w][k]); 9 taps of K=128.
#define CM_WH 0
#define CM_WL (128 * 68)
#define CM_XH (2 * 128 * 68)
#define CM_XL (2 * 128 * 68 + 64 * 68)
#define CONV_SMEM ((2 * 128 * 68 + 2 * 64 * 68) * 4)

template <int MODE>
__global__ void __launch_bounds__(256, 2) conv_mma_k(
        const __nv_bfloat16* __restrict__ athi, const __nv_bfloat16* __restrict__ atlo,
        const __nv_bfloat16* __restrict__ whi,  const __nv_bfloat16* __restrict__ wlo,
        const float* __restrict__ bias, const float* __restrict__ temb,
        const float* __restrict__ resid, float* __restrict__ dst) {
    extern __shared__ __align__(16) unsigned smc[];
    unsigned* Wh = smc + CM_WH;
    unsigned* Wl = smc + CM_WL;
    unsigned* Xh = smc + CM_XH;
    unsigned* Xl = smc + CM_XL;
    int t = threadIdx.x, lane = t & 31, wid = t >> 5;
    int h = blockIdx.x, b = blockIdx.y;
    int g = lane >> 2, tq = lane & 3;
    int mrow = wid * 16;

    float o[8][4];
#pragma unroll
    for (int n = 0; n < 8; n++)
#pragma unroll
        for (int k = 0; k < 4; k++) o[n][k] = 0.f;

    for (int tap = 0; tap < 9; tap++) {
        int kh = tap / 3, kw = tap % 3;
        int hh = h + kh - 1;
        if (hh < 0 || hh > 63) continue;              // block-uniform
        __syncthreads();
        // ---- X tile: act rows, zero-padded at w edges ----
#pragma unroll
        for (int i = 0; i < 4; i++) {
            int idx = t + i * 256;                    // 1024: w(64) x q(16)
            int w = idx >> 4, q = idx & 15;
            int ws = w + kw - 1;
            uint4 vh = make_uint4(0, 0, 0, 0), vl = make_uint4(0, 0, 0, 0);
            if (ws >= 0 && ws < 64) {
                size_t gi = ((size_t)((b * 64 + hh) * 64 + ws)) * 128 + q * 8;
                vh = *(const uint4*)(athi + gi);
                vl = *(const uint4*)(atlo + gi);
            }
            *(uint4*)(Xh + w * 68 + q * 4) = vh;
            *(uint4*)(Xl + w * 68 + q * 4) = vl;
        }
        // ---- W tile ----
#pragma unroll
        for (int i = 0; i < 8; i++) {
            int idx = t + i * 256;                    // 2048: co(128) x q(16)
            int co = idx >> 4, q = idx & 15;
            size_t gi = (size_t)(kh * 128 + co) * 384 + kw * 128 + q * 8;
            *(uint4*)(Wh + co * 68 + q * 4) = *(const uint4*)(whi + gi);
            *(uint4*)(Wl + co * 68 + q * 4) = *(const uint4*)(wlo + gi);
        }
        __syncthreads();
        // ---- GEMM chunk: M=128co, N=64w, K=128ci (3-term split) ----
#pragma unroll
        for (int ks = 0; ks < 8; ks++) {
            int r0 = (mrow + g) * 68 + 8 * ks + tq, r1 = r0 + 8 * 68;
            unsigned wh0 = Wh[r0], wh1 = Wh[r1], wh2 = Wh[r0 + 4], wh3 = Wh[r1 + 4];
            unsigned wl0 = Wl[r0], wl1 = Wl[r1], wl2 = Wl[r0 + 4], wl3 = Wl[r1 + 4];
#pragma unroll
            for (int n = 0; n < 8; n++) {
                int bi = (8 * n + g) * 68 + 8 * ks + tq;
                unsigned xh0 = Xh[bi], xh1 = Xh[bi + 4];
                unsigned xl0 = Xl[bi], xl1 = Xl[bi + 4];
                mma16816(o[n], wh0, wh1, wh2, wh3, xh0, xh1);
                mma16816(o[n], wh0, wh1, wh2, wh3, xl0, xl1);
                mma16816(o[n], wl0, wl1, wl2, wl3, xh0, xh1);
            }
        }
    }
    // ---- epilogue ----
    int co0 = mrow + g;
    float add0 = bias[co0]     + (MODE == 0 ? temb[b * 128 + co0]     : 0.f);
    float add1 = bias[co0 + 8] + (MODE == 0 ? temb[b * 128 + co0 + 8] : 0.f);
#pragma unroll
    for (int n = 0; n < 8; n++) {
        int w = 8 * n + 2 * tq;
        size_t i0 = ((size_t)(b * 128 + co0) * 64 + h) * 64 + w;
        size_t i1 = i0 + 8 * 4096;
        float v00 = o[n][0] + add0, v01 = o[n][1] + add0;
        float v10 = o[n][2] + add1, v11 = o[n][3] + add1;
        if (MODE == 1) {
            v00 += resid[i0]; v01 += resid[i0 + 1];
            v10 += resid[i1]; v11 += resid[i1 + 1];
        }
        *(float2*)(dst + i0) = make_float2(v00, v01);
        *(float2*)(dst + i1) = make_float2(v10, v11);
    }
}

// ------------------------- cond 1x1 projection -------------------------
__global__ void __launch_bounds__(256) cond1x1_k(const float* __restrict__ cond,
                                                 const float* __restrict__ wt,
                                                 const float* __restrict__ bias,
                                                 float* __restrict__ out) {
    __shared__ float ct[128 * 64];
    int uv0 = blockIdx.x * 64;
    int b = blockIdx.y, t = threadIdx.x;
    for (int i = 0; i < 32; i++) {
        int idx = t + i * 256;
        ct[idx] = cond[(b * 128 + (idx >> 6)) * 4096 + uv0 + (idx & 63)];
    }
    __syncthreads();
    int co = t & 127, uh = t >> 7;
    ull acc[16];
#pragma unroll
    for (int j = 0; j < 16; j++) acc[j] = 0ull;
    const float* wrow = wt + co * 128;
    for (int ci = 0; ci < 128; ci++) {
        ull wv = dup2(__ldg(wrow + ci));
        const ull* kr = (const ull*)&ct[ci * 64 + uh * 32];
#pragma unroll
        for (int j = 0; j < 16; j++) fma2(acc[j], wv, kr[j]);
    }
    float bv = bias[co];
    float* op = out + (b * 128 + co) * 4096 + uv0 + uh * 32;
#pragma unroll
    for (int j = 0; j < 16; j++) {
        float2 v = unp2(acc[j]);
        op[2 * j]     = v.x + bv;
        op[2 * j + 1] = v.y + bv;
    }
}

// ------------------------- K split -------------------------
__global__ void __launch_bounds__(256) ksplit_k(const float* __restrict__ cbuf,
                                                __nv_bfloat16* __restrict__ khi,
                                                __nv_bfloat16* __restrict__ klo,
                                                __nv_bfloat16* __restrict__ kthi,
                                                __nv_bfloat16* __restrict__ ktlo) {
    __shared__ float ct[128 * 65];
    int u0 = blockIdx.x * 64, b = blockIdx.y, t = threadIdx.x;
    for (int i = 0; i < 32; i++) {
        int idx = t + i * 256;
        int c = idx >> 6, u = idx & 63;
        ct[c * 65 + u] = cbuf[(b * 128 + c) * 4096 + u0 + u];
    }
    __syncthreads();
    {
        int c = t >> 1, uh = (t & 1) * 32;
        unsigned hi[16], lo[16];
#pragma unroll
        for (int j = 0; j < 16; j++) {
            float f0 = ct[c * 65 + uh + 2 * j], f1 = ct[c * 65 + uh + 2 * j + 1];
            float h0 = __bfloat162float(__float2bfloat16(f0));
            float h1 = __bfloat162float(__float2bfloat16(f1));
            hi[j] = pack_bf16(h0, h1);
            lo[j] = pack_bf16(f0 - h0, f1 - h1);
        }
        uint4* dh = (uint4*)(khi + (size_t)(b * 128 + c) * 4096 + u0 + uh);
        uint4* dl = (uint4*)(klo + (size_t)(b * 128 + c) * 4096 + u0 + uh);
#pragma unroll
        for (int q = 0; q < 4; q++) {
            dh[q] = make_uint4(hi[4*q], hi[4*q+1], hi[4*q+2], hi[4*q+3]);
            dl[q] = make_uint4(lo[4*q], lo[4*q+1], lo[4*q+2], lo[4*q+3]);
        }
    }
    {
        int u = t & 63, ch = (t >> 6) * 32;
        unsigned hi[16], lo[16];
#pragma unroll
        for (int j = 0; j < 16; j++) {
            float f0 = ct[(ch + 2 * j) * 65 + u], f1 = ct[(ch + 2 * j + 1) * 65 + u];
            float h0 = __bfloat162float(__float2bfloat16(f0));
            float h1 = __bfloat162float(__float2bfloat16(f1));
            hi[j] = pack_bf16(h0, h1);
            lo[j] = pack_bf16(f0 - h0, f1 - h1);
        }
        uint4* dh = (uint4*)(kthi + (size_t)(b * 4096 + u0 + u) * 128 + ch);
        uint4* dl = (uint4*)(ktlo + (size_t)(b * 4096 + u0 + u) * 128 + ch);
#pragma unroll
        for (int q = 0; q < 4; q++) {
            dh[q] = make_uint4(hi[4*q], hi[4*q+1], hi[4*q+2], hi[4*q+3]);
            dl[q] = make_uint4(lo[4*q], lo[4*q+1], lo[4*q+2], lo[4*q+3]);
        }
    }
}

// ------------------------- transpose + scale: h1 -> h1T -------------------------
__global__ void __launch_bounds__(256) transpose_k(const float* __restrict__ h1,
                                                   float* __restrict__ h1T) {
    __shared__ float sm[128 * 65];
    int h = blockIdx.x, b = blockIdx.y, t = threadIdx.x;
    const float* src = h1 + ((b * 128) * 64 + h) * 64;
    for (int i = 0; i < 32; i++) {
        int idx = t + i * 256;
        int c = idx >> 6, w = idx & 63;
        sm[c * 65 + w] = src[c * 4096 + w] * SCALE_Q;
    }
    __syncthreads();
    for (int i = 0; i < 32; i++) {
        int idx = t + i * 256;
        int w = idx >> 7, c = idx & 127;
        h1T[((b * 64 + w) * 64 + h) * 128 + c] = sm[c * 65 + w];
    }
}

// ------------------------- prefill: h2 = h1 + contrast_embed[aim[b]] -------------------------
__global__ void __launch_bounds__(256) prefill_k(const float* __restrict__ h1,
                                                 const float* __restrict__ emb,
                                                 const int* __restrict__ aim,
                                                 float* __restrict__ h2) {
    int i = blockIdx.x * 256 + threadIdx.x;
    int b = i >> 17, c = (i >> 10) & 127;
    float e = emb[aim[b] * 128 + c];
    float4 v = ((const float4*)h1)[i];
    v.x += e; v.y += e; v.z += e; v.w += e;
    ((float4*)h2)[i] = v;
}

// ------------------------- transadd: h2[b][c][h][w] += oT[b][w][h][c] -------------------------
__global__ void __launch_bounds__(256) transadd_k(const float* __restrict__ oT,
                                                  float* __restrict__ h2) {
    __shared__ float sm[64 * 129];
    int h = blockIdx.x, b = blockIdx.y, t = threadIdx.x;
    for (int i = 0; i < 32; i++) {
        int idx = t + i * 256;
        int w = idx >> 7, c = idx & 127;
        sm[w * 129 + c] = oT[((b * 64 + w) * 64 + h) * 128 + c];
    }
    __syncthreads();
    for (int i = 0; i < 32; i++) {
        int idx = t + i * 256;
        int c = idx >> 6, w = idx & 63;
        h2[((b * 128 + c) * 64 + h) * 64 + w] += sm[w * 129 + c];
    }
}

// ------------------------- mma.sync attention (R10, unchanged) -------------------------
#define OFF_AHI  0
#define OFF_ALO  (OFF_AHI + 128 * 68 * 4)
#define OFF_KTHI (OFF_ALO + 128 * 68 * 4)
#define OFF_KTLO (OFF_KTHI + 64 * 68 * 4)
#define OFF_KCHI (OFF_KTLO + 64 * 68 * 4)
#define OFF_KCLO (OFF_KCHI + 128 * 36 * 4)
#define OFF_SST  (OFF_KCLO + 128 * 36 * 4)
#define OFF_REDS (OFF_SST + 64 * 129 * 4)
#define OFF_RSM  (OFF_REDS + 256 * 4)
#define OFF_PHI  (OFF_RSM + 128 * 4)
#define OFF_PLO  (OFF_PHI + 128 * 36 * 4)
#define ATTN_SMEM (OFF_PLO + 128 * 36 * 4)

__global__ void __launch_bounds__(256, 1) attn_mma_k(const float* __restrict__ h1T,
        const __nv_bfloat16* __restrict__ khi, const __nv_bfloat16* __restrict__ klo,
        const __nv_bfloat16* __restrict__ kthi, const __nv_bfloat16* __restrict__ ktlo,
        float* __restrict__ oT) {
    extern __shared__ __align__(16) char sm[];
    unsigned* Ahi  = (unsigned*)(sm + OFF_AHI);
    unsigned* Alo  = (unsigned*)(sm + OFF_ALO);
    unsigned* KThi = (unsigned*)(sm + OFF_KTHI);
    unsigned* KTlo = (unsigned*)(sm + OFF_KTLO);
    unsigned* Kchi = (unsigned*)(sm + OFF_KCHI);
    unsigned* Kclo = (unsigned*)(sm + OFF_KCLO);
    float*    SsT  = (float*)(sm + OFF_SST);
    float*    reds = (float*)(sm + OFF_REDS);
    float*    rsm  = (float*)(sm + OFF_RSM);
    unsigned* Phi  = (unsigned*)(sm + OFF_PHI);
    unsigned* Plo  = (unsigned*)(sm + OFF_PLO);

    int t = threadIdx.x, lane = t & 31, wid = t >> 5;
    int wp = blockIdx.x, b = blockIdx.y;
    int g = lane >> 2, tq = lane & 3;
    int mrow = wid * 16;

    {
        int m = t >> 1, ch = (t & 1) * 64;
        const float* ar = h1T + (size_t)((b * 64 + 2 * wp + (m >> 6)) * 64 + (m & 63)) * 128 + ch;
        unsigned* dh = Ahi + m * 68 + (ch >> 1);
        unsigned* dl = Alo + m * 68 + (ch >> 1);
#pragma unroll
        for (int j = 0; j < 32; j++) {
            float f0 = ar[2 * j], f1 = ar[2 * j + 1];
            float h0 = __bfloat162float(__float2bfloat16(f0));
            float h1 = __bfloat162float(__float2bfloat16(f1));
            dh[j] = pack_bf16(h0, h1);
            dl[j] = pack_bf16(f0 - h0, f1 - h1);
        }
    }

    float o[16][4];
#pragma unroll
    for (int n = 0; n < 16; n++)
#pragma unroll
        for (int k = 0; k < 4; k++) o[n][k] = 0.f;

    for (int tile = 0; tile < 64; tile++) {
        int u0 = tile * 64;
        __syncthreads();
#pragma unroll
        for (int i = 0; i < 4; i++) {
            int cidx = t + i * 256;
            {
                int u = cidx >> 4, q = cidx & 15;
                const uint4* sh = (const uint4*)(kthi + (size_t)(b * 4096 + u0 + u) * 128 + q * 8);
                const uint4* sl = (const uint4*)(ktlo + (size_t)(b * 4096 + u0 + u) * 128 + q * 8);
                *(uint4*)(KThi + u * 68 + q * 4) = *sh;
                *(uint4*)(KTlo + u * 68 + q * 4) = *sl;
            }
            {
                int c = cidx >> 3, q = cidx & 7;
                const uint4* sh = (const uint4*)(khi + (size_t)(b * 128 + c) * 4096 + u0 + q * 8);
                const uint4* sl = (const uint4*)(klo + (size_t)(b * 128 + c) * 4096 + u0 + q * 8);
                *(uint4*)(Kchi + c * 36 + q * 4) = *sh;
                *(uint4*)(Kclo + c * 36 + q * 4) = *sl;
            }
        }
        __syncthreads();

        float s[8][4];
#pragma unroll
        for (int n = 0; n < 8; n++)
#pragma unroll
            for (int k = 0; k < 4; k++) s[n][k] = 0.f;
#pragma unroll
        for (int ks = 0; ks < 8; ks++) {
            int r0 = (mrow + g) * 68 + 8 * ks + tq;
            int r1 = (mrow + g + 8) * 68 + 8 * ks + tq;
            unsigned ah0 = Ahi[r0], ah1 = Ahi[r1], ah2 = Ahi[r0 + 4], ah3 = Ahi[r1 + 4];
            unsigned al0 = Alo[r0], al1 = Alo[r1], al2 = Alo[r0 + 4], al3 = Alo[r1 + 4];
#pragma unroll
            for (int n = 0; n < 8; n++) {
                int bi = (8 * n + g) * 68 + 8 * ks + tq;
                unsigned bh0 = KThi[bi], bh1 = KThi[bi + 4];
                unsigned bl0 = KTlo[bi], bl1 = KTlo[bi + 4];
                mma16816(s[n], ah0, ah1, ah2, ah3, bh0, bh1);
                mma16816(s[n], ah0, ah1, ah2, ah3, bl0, bl1);
                mma16816(s[n], al0, al1, al2, al3, bh0, bh1);
            }
        }
#pragma unroll
        for (int n = 0; n < 8; n++) {
            int ub = 8 * n + 2 * tq;
            SsT[ub * 129 + mrow + g]           = s[n][0];
            SsT[(ub + 1) * 129 + mrow + g]     = s[n][1];
            SsT[ub * 129 + mrow + g + 8]       = s[n][2];
            SsT[(ub + 1) * 129 + mrow + g + 8] = s[n][3];
        }
        __syncthreads();

        {
            int u = t & 63, qq = t >> 6;
            float* col = SsT + u * 129 + qq * 32;
            float ps = 0.f;
#pragma unroll
            for (int j = 0; j < 32; j++) {
                float e = __expf(col[j]);
                col[j] = e;
                ps += e;
            }
            reds[qq * 64 + u] = ps;
        }
        __syncthreads();
        if (t < 128) {
            int half = t >> 6, u = t & 63;
            rsm[half * 64 + u] = 1.f / (reds[2 * half * 64 + u] + reds[(2 * half + 1) * 64 + u]);
        }
        __syncthreads();

        {
            int m = t >> 1, uh = (t & 1) * 32, half = m >> 6;
            const float* rp = rsm + half * 64;
            unsigned* ph = Phi + m * 36 + (uh >> 1);
            unsigned* pl = Plo + m * 36 + (uh >> 1);
#pragma unroll
            for (int j = 0; j < 16; j++) {
                int u = uh + 2 * j;
                float p0 = SsT[u * 129 + m] * rp[u];
                float p1 = SsT[(u + 1) * 129 + m] * rp[u + 1];
                float h0 = __bfloat162float(__float2bfloat16(p0));
                float h1 = __bfloat162float(__float2bfloat16(p1));
                ph[j] = pack_bf16(h0, h1);
                pl[j] = pack_bf16(p0 - h0, p1 - h1);
            }
        }
        __syncthreads();

#pragma unroll
        for (int ks = 0; ks < 4; ks++) {
            int r0 = (mrow + g) * 36 + 8 * ks + tq;
            int r1 = (mrow + g + 8) * 36 + 8 * ks + tq;
            unsigned ph0 = Phi[r0], ph1 = Phi[r1], ph2 = Phi[r0 + 4], ph3 = Phi[r1 + 4];
            unsigned pl0 = Plo[r0], pl1 = Plo[r1], pl2 = Plo[r0 + 4], pl3 = Plo[r1 + 4];
#pragma unroll
            for (int n = 0; n < 16; n++) {
                int bi = (8 * n + g) * 36 + 8 * ks + tq;
                unsigned bh0 = Kchi[bi], bh1 = Kchi[bi + 4];
                unsigned bl0 = Kclo[bi], bl1 = Kclo[bi + 4];
                mma16816(o[n], ph0, ph1, ph2, ph3, bh0, bh1);
                mma16816(o[n], ph0, ph1, ph2, ph3, bl0, bl1);
                mma16816(o[n], pl0, pl1, pl2, pl3, bh0, bh1);
            }
        }
    }

    {
        size_t base = (size_t)(b * 64 + 2 * wp + (mrow >> 6)) * 64;
        int hrow = (mrow & 63) + g;
        float* r0 = oT + (base + hrow) * 128;
        float* r1 = oT + (base + hrow + 8) * 128;
#pragma unroll
        for (int n = 0; n < 16; n++) {
            *(float2*)(r0 + 8 * n + 2 * tq) = make_float2(o[n][0], o[n][1]);
            *(float2*)(r1 + 8 * n + 2 * tq) = make_float2(o[n][2], o[n][3]);
        }
    }
}

// ------------------------- launch -------------------------
extern "C" void kernel_launch(void* const* d_in, const int* in_sizes, int n_in,
                              void* d_out, int out_size) {
    const float* x    = (const float*)d_in[0];
    const float* tt   = (const float*)d_in[1];
    const int*   aim  = (const int*)d_in[2];
    const float* cond = (const float*)d_in[3];
    const float* g1s  = (const float*)d_in[4];
    const float* g1b  = (const float*)d_in[5];
    const float* c1w  = (const float*)d_in[6];
    const float* c1b  = (const float*)d_in[7];
    const float* mw   = (const float*)d_in[8];
    const float* mb   = (const float*)d_in[9];
    const float* cw   = (const float*)d_in[10];
    const float* cbi  = (const float*)d_in[11];
    const float* g2s  = (const float*)d_in[12];
    const float* g2b  = (const float*)d_in[13];
    const float* c2w  = (const float*)d_in[14];
    const float* c2b  = (const float*)d_in[15];
    const float* emb  = (const float*)d_in[16];
    float* out = (float*)d_out;

    float *act, *h1, *h1T, *cbuf, *h2, *oT, *temb, *mean, *rstd;
    __nv_bfloat16 *khi, *klo, *kthi, *ktlo, *athi, *atlo, *whi, *wlo;
    cudaGetSymbolAddress((void**)&act,  g_act);
    cudaGetSymbolAddress((void**)&h1,   g_h1);
    cudaGetSymbolAddress((void**)&h1T,  g_h1T);
    cudaGetSymbolAddress((void**)&cbuf, g_cbuf);
    cudaGetSymbolAddress((void**)&h2,   g_h2);
    cudaGetSymbolAddress((void**)&oT,   g_oT);
    cudaGetSymbolAddress((void**)&temb, g_temb);
    cudaGetSymbolAddress((void**)&mean, g_mean);
    cudaGetSymbolAddress((void**)&rstd, g_rstd);
    cudaGetSymbolAddress((void**)&khi,  g_khi);
    cudaGetSymbolAddress((void**)&klo,  g_klo);
    cudaGetSymbolAddress((void**)&kthi, g_kthi);
    cudaGetSymbolAddress((void**)&ktlo, g_ktlo);
    cudaGetSymbolAddress((void**)&athi, g_athi);
    cudaGetSymbolAddress((void**)&atlo, g_atlo);
    cudaGetSymbolAddress((void**)&whi,  g_whi);
    cudaGetSymbolAddress((void**)&wlo,  g_wlo);

    cudaFuncSetAttribute(attn_mma_k, cudaFuncAttributeMaxDynamicSharedMemorySize, ATTN_SMEM);
    cudaFuncSetAttribute(conv_mma_k<0>, cudaFuncAttributeMaxDynamicSharedMemorySize, CONV_SMEM);
    cudaFuncSetAttribute(conv_mma_k<1>, cudaFuncAttributeMaxDynamicSharedMemorySize, CONV_SMEM);

    gn_stats_k<<<128, 256>>>(x, mean, rstd);
    gn_apply_k<<<2048, 256>>>(x, mean, rstd, g1s, g1b, act);
    actsplit_k<<<dim3(64, 4), 256>>>(act, athi, atlo);
    wsplit_k<<<576, 256>>>(c1w, whi, wlo);
    temb_k<<<4, 128>>>(tt, mw, mb, temb);
    conv_mma_k<0><<<dim3(64, 4), 256, CONV_SMEM>>>(athi, atlo, whi, wlo, c1b, temb, nullptr, h1);
    cond1x1_k<<<dim3(64, 4), 256>>>(cond, cw, cbi, cbuf);
    ksplit_k<<<dim3(64, 4), 256>>>(cbuf, khi, klo, kthi, ktlo);
    transpose_k<<<dim3(64, 4), 256>>>(h1, h1T);
    prefill_k<<<2048, 256>>>(h1, emb, aim, h2);
    attn_mma_k<<<dim3(32, 4), 256, ATTN_SMEM>>>(h1T, khi, klo, kthi, ktlo, oT);
    transadd_k<<<dim3(64, 4), 256>>>(oT, h2);
    gn_stats_k<<<128, 256>>>(h2, mean, rstd);
    gn_apply_k<<<2048, 256>>>(h2, mean, rstd, g2s, g2b, act);
    actsplit_k<<<dim3(64, 4), 256>>>(act, athi, atlo);
    wsplit_k<<<576, 256>>>(c2w, whi, wlo);
    conv_mma_k<1><<<dim3(64, 4), 256, CONV_SMEM>>>(athi, atlo, whi, wlo, c2b, nullptr, x, out);
}

// round 13
// speedup vs baseline: 2.6470x; 1.2668x over previous
#include <cuda_runtime.h>
#include <cuda_fp16.h>
#include <math.h>
#include <stdint.h>

typedef unsigned long long ull;

#define NB 4
#define NC 128
#define NHW 4096
#define NG 32
#define NTD 512
#define SCALE_Q 0.088388347648318447f  /* 1/sqrt(128) */

// ------------------------- static scratch (no allocations) -------------------------
static __device__ float  g_h1  [NB * NC * NHW];
static __device__ float  g_h2  [NB * NC * NHW];
static __device__ float  g_oT  [NB * NHW * NC];   // attn out [b][w][h][c]
static __device__ float  g_temb[NB * NC];
static __device__ float  g_mean[NB * NG];
static __device__ float  g_rstd[NB * NG];
static __device__ __half g_h1T [NB * NHW * NC];   // [b][w][h][c] * 1/sqrt(C), fp16
static __device__ __half g_khi [NB * NC * NHW];   // K [b][c][u] hi
static __device__ __half g_klo [NB * NC * NHW];   // K [b][c][u] lo
static __device__ __half g_kthi[NB * NHW * NC];   // K [b][u][c] hi
static __device__ __half g_ktlo[NB * NHW * NC];   // K [b][u][c] lo
static __device__ __half g_athi[NB * NHW * NC];   // act [b][h][w][c] hi
static __device__ __half g_atlo[NB * NHW * NC];   // act [b][h][w][c] lo
static __device__ __half g_wh  [3 * 128 * 384];   // weights [kh][co][kw*128+ci] (fp16 round)

// ------------------------- helpers -------------------------
__device__ __forceinline__ void fma2(ull& d, ull a, ull b) {
    asm("fma.rn.f32x2 %0, %1, %2, %0;" : "+l"(d) : "l"(a), "l"(b));
}
__device__ __forceinline__ ull dup2(float x) {
    ull r;
    asm("mov.b64 %0, {%1, %2};" : "=l"(r) : "f"(x), "f"(x));
    return r;
}
__device__ __forceinline__ float2 unp2(ull v) {
    float2 r;
    asm("mov.b64 {%0, %1}, %2;" : "=f"(r.x), "=f"(r.y) : "l"(v));
    return r;
}
__device__ __forceinline__ float siluf(float x) { return x / (1.0f + __expf(-x)); }

__device__ __forceinline__ unsigned packh2(float a, float b) {
    __half2 t = __floats2half2_rn(a, b);
    return *reinterpret_cast<unsigned*>(&t);
}

// fp16 HMMA m16n8k16 (family-safe PTX, f32 accum)
__device__ __forceinline__ void mma_h(float* d, unsigned a0, unsigned a1,
                                      unsigned a2, unsigned a3,
                                      unsigned b0, unsigned b1) {
    asm volatile(
        "mma.sync.aligned.m16n8k16.row.col.f32.f16.f16.f32 "
        "{%0,%1,%2,%3}, {%4,%5,%6,%7}, {%8,%9}, {%0,%1,%2,%3};"
        : "+f"(d[0]), "+f"(d[1]), "+f"(d[2]), "+f"(d[3])
        : "r"(a0), "r"(a1), "r"(a2), "r"(a3), "r"(b0), "r"(b1));
}

// ------------------------- group-norm statistics -------------------------
__global__ void __launch_bounds__(256) gn_stats_k(const float* __restrict__ src,
                                                  float* __restrict__ mean,
                                                  float* __restrict__ rstd) {
    int bg = blockIdx.x;
    const float4* p = (const float4*)(src + bg * 16384);
    float s = 0.f, ss = 0.f;
    for (int i = threadIdx.x; i < 4096; i += 256) {
        float4 v = p[i];
        s  += v.x + v.y + v.z + v.w;
        ss += v.x * v.x + v.y * v.y + v.z * v.z + v.w * v.w;
    }
    for (int off = 16; off; off >>= 1) {
        s  += __shfl_down_sync(0xffffffffu, s,  off);
        ss += __shfl_down_sync(0xffffffffu, ss, off);
    }
    __shared__ float ws[8], wss[8];
    int wid = threadIdx.x >> 5, lane = threadIdx.x & 31;
    if (lane == 0) { ws[wid] = s; wss[wid] = ss; }
    __syncthreads();
    if (threadIdx.x == 0) {
        float ts = 0.f, tss = 0.f;
        for (int i = 0; i < 8; i++) { ts += ws[i]; tss += wss[i]; }
        float m = ts * (1.f / 16384.f);
        float var = tss * (1.f / 16384.f) - m * m;
        mean[bg] = m;
        rstd[bg] = rsqrtf(var + 1e-5f);
    }
}

// ------------- GN + SiLU + transpose + fp16 split: src[b][c][h][w] -> at{hi,lo}[b][h][w][c] ---
__global__ void __launch_bounds__(256) gnact_k(const float* __restrict__ src,
                                               const float* __restrict__ mean,
                                               const float* __restrict__ rstd,
                                               const float* __restrict__ sc,
                                               const float* __restrict__ bi,
                                               __half* __restrict__ athi,
                                               __half* __restrict__ atlo) {
    __shared__ float smt[128 * 65];
    __shared__ float a_s[128], b_s[128];
    int h = blockIdx.x, b = blockIdx.y, t = threadIdx.x;
    if (t < 128) {
        float a = rstd[b * 32 + (t >> 2)] * sc[t];
        a_s[t] = a;
        b_s[t] = bi[t] - mean[b * 32 + (t >> 2)] * a;
    }
    __syncthreads();
    for (int i = 0; i < 32; i++) {
        int idx = t + i * 256;
        int c = idx >> 6, w = idx & 63;
        float v = src[(b * 128 + c) * 4096 + h * 64 + w];
        smt[c * 65 + w] = siluf(v * a_s[c] + b_s[c]);
    }
    __syncthreads();
    unsigned* oh = (unsigned*)(athi + (size_t)(b * 64 + h) * 64 * 128);
    unsigned* ol = (unsigned*)(atlo + (size_t)(b * 64 + h) * 64 * 128);
    for (int i = 0; i < 16; i++) {
        int idx = t + i * 256;                        // 4096 u32
        int w = idx >> 6, cp = idx & 63;
        float f0 = smt[(2 * cp) * 65 + w], f1 = smt[(2 * cp + 1) * 65 + w];
        float h0 = __half2float(__float2half_rn(f0));
        float h1 = __half2float(__float2half_rn(f1));
        oh[w * 64 + cp] = packh2(h0, h1);
        ol[w * 64 + cp] = packh2(f0 - h0, f1 - h1);
    }
}

// ------------------------- weight reorder + fp16 round: [co][ci][3][3] -> [kh][co][kw*128+ci] ---
__global__ void __launch_bounds__(256) wround_k(const float* __restrict__ wgt,
                                                __half* __restrict__ wh) {
    int o = blockIdx.x * 256 + threadIdx.x;          // 147456 outputs
    int kh = o / 49152, r = o % 49152;
    int co = r / 384,  r2 = r % 384;
    int kw = r2 >> 7,  ci = r2 & 127;
    wh[o] = __float2half_rn(wgt[((co * 128 + ci) * 3 + kh) * 3 + kw]);
}

// ------------------------- time embedding -------------------------
__global__ void __launch_bounds__(128) temb_k(const float* __restrict__ t,
                                              const float* __restrict__ mw,
                                              const float* __restrict__ mb,
                                              float* __restrict__ temb) {
    __shared__ float st[NTD];
    int b = blockIdx.x, tid = threadIdx.x;
    for (int k = tid; k < NTD; k += 128) st[k] = siluf(t[b * NTD + k]);
    __syncthreads();
    float acc = mb[tid];
    const float* wr = mw + tid * NTD;
#pragma unroll 8
    for (int k = 0; k < NTD; k++) acc += st[k] * wr[k];
    temb[b * NC + tid] = acc;
}

// ------------------------- tensor-core 3x3 conv: block per (b,h); 2 MMAs per product --------
// A = W (fp16 round, row-major [co][k]); B = x (fp16 hi+lo, col-major [w][k]); 9 taps K=128.
#define CV_WH 0
#define CV_XH (128 * 68)
#define CV_XL (128 * 68 + 64 * 68)
#define CONV_SMEM ((128 * 68 + 2 * 64 * 68) * 4)

template <int MODE>
__global__ void __launch_bounds__(256, 2) conv_mma_k(
        const __half* __restrict__ athi, const __half* __restrict__ atlo,
        const __half* __restrict__ wh,
        const float* __restrict__ bias, const float* __restrict__ temb,
        const float* __restrict__ resid, float* __restrict__ dst) {
    extern __shared__ __align__(16) unsigned smc[];
    unsigned* Wh = smc + CV_WH;
    unsigned* Xh = smc + CV_XH;
    unsigned* Xl = smc + CV_XL;
    int t = threadIdx.x, lane = t & 31, wid = t >> 5;
    int h = blockIdx.x, b = blockIdx.y;
    int g = lane >> 2, tq = lane & 3;
    int mrow = wid * 16;

    float o[8][4];
#pragma unroll
    for (int n = 0; n < 8; n++)
#pragma unroll
        for (int k = 0; k < 4; k++) o[n][k] = 0.f;

    for (int tap = 0; tap < 9; tap++) {
        int kh = tap / 3, kw = tap % 3;
        int hh = h + kh - 1;
        if (hh < 0 || hh > 63) continue;              // block-uniform
        __syncthreads();
        // X tiles (hi/lo), zero-padded at w edges
#pragma unroll
        for (int i = 0; i < 4; i++) {
            int idx = t + i * 256;                    // 1024: w(64) x q(16)
            int w = idx >> 4, q = idx & 15;
            int ws = w + kw - 1;
            uint4 vh = make_uint4(0, 0, 0, 0), vl = make_uint4(0, 0, 0, 0);
            if (ws >= 0 && ws < 64) {
                size_t gi = (size_t)((b * 64 + hh) * 64 + ws) * 16 + q;
                vh = ((const uint4*)athi)[gi];
                vl = ((const uint4*)atlo)[gi];
            }
            *(uint4*)(Xh + w * 68 + q * 4) = vh;
            *(uint4*)(Xl + w * 68 + q * 4) = vl;
        }
        // W tile
#pragma unroll
        for (int i = 0; i < 8; i++) {
            int idx = t + i * 256;                    // 2048: co(128) x q(16)
            int co = idx >> 4, q = idx & 15;
            *(uint4*)(Wh + co * 68 + q * 4) =
                ((const uint4*)wh)[(size_t)(kh * 128 + co) * 48 + kw * 16 + q];
        }
        __syncthreads();
#pragma unroll
        for (int ks = 0; ks < 8; ks++) {
            int r0 = (mrow + g) * 68 + 8 * ks + tq, r1 = r0 + 8 * 68;
            unsigned a0 = Wh[r0], a1 = Wh[r1], a2 = Wh[r0 + 4], a3 = Wh[r1 + 4];
#pragma unroll
            for (int n = 0; n < 8; n++) {
                int bi = (8 * n + g) * 68 + 8 * ks + tq;
                unsigned xh0 = Xh[bi], xh1 = Xh[bi + 4];
                unsigned xl0 = Xl[bi], xl1 = Xl[bi + 4];
                mma_h(o[n], a0, a1, a2, a3, xh0, xh1);
                mma_h(o[n], a0, a1, a2, a3, xl0, xl1);
            }
        }
    }
    int co0 = mrow + g;
    float add0 = bias[co0]     + (MODE == 0 ? temb[b * 128 + co0]     : 0.f);
    float add1 = bias[co0 + 8] + (MODE == 0 ? temb[b * 128 + co0 + 8] : 0.f);
#pragma unroll
    for (int n = 0; n < 8; n++) {
        int w = 8 * n + 2 * tq;
        size_t i0 = ((size_t)(b * 128 + co0) * 64 + h) * 64 + w;
        size_t i1 = i0 + 8 * 4096;
        float v00 = o[n][0] + add0, v01 = o[n][1] + add0;
        float v10 = o[n][2] + add1, v11 = o[n][3] + add1;
        if (MODE == 1) {
            v00 += resid[i0]; v01 += resid[i0 + 1];
            v10 += resid[i1]; v11 += resid[i1 + 1];
        }
        *(float2*)(dst + i0) = make_float2(v00, v01);
        *(float2*)(dst + i1) = make_float2(v10, v11);
    }
}

// --------------- cond 1x1 projection + fp16 split, both orientations (fused) ---------------
#define COND_SMEM ((128 * 64 + 128 * 65) * 4)
__global__ void __launch_bounds__(256) cond1x1s_k(const float* __restrict__ cond,
                                                  const float* __restrict__ wt,
                                                  const float* __restrict__ bias,
                                                  __half* __restrict__ khi,
                                                  __half* __restrict__ klo,
                                                  __half* __restrict__ kthi,
                                                  __half* __restrict__ ktlo) {
    extern __shared__ __align__(16) float smf[];
    float* ct = smf;                 // [128ci][64u]
    float* ss = smf + 128 * 64;      // [128co][65]
    int u0 = blockIdx.x * 64, b = blockIdx.y, t = threadIdx.x;
    for (int i = 0; i < 32; i++) {
        int idx = t + i * 256;
        ct[idx] = cond[(b * 128 + (idx >> 6)) * 4096 + u0 + (idx & 63)];
    }
    __syncthreads();
    {
        int co = t & 127, uh = t >> 7;
        ull acc[16];
#pragma unroll
        for (int j = 0; j < 16; j++) acc[j] = 0ull;
        const float* wrow = wt + co * 128;
        for (int ci = 0; ci < 128; ci++) {
            ull wv = dup2(__ldg(wrow + ci));
            const ull* kr = (const ull*)&ct[ci * 64 + uh * 32];
#pragma unroll
            for (int j = 0; j < 16; j++) fma2(acc[j], wv, kr[j]);
        }
        float bv = bias[co];
        float* op = ss + co * 65 + uh * 32;
#pragma unroll
        for (int j = 0; j < 16; j++) {
            float2 v = unp2(acc[j]);
            op[2 * j]     = v.x + bv;
            op[2 * j + 1] = v.y + bv;
        }
    }
    __syncthreads();
    {   // [c][u] orientation
        int c = t >> 1, uh = (t & 1) * 32;
        unsigned hi[16], lo[16];
#pragma unroll
        for (int j = 0; j < 16; j++) {
            float f0 = ss[c * 65 + uh + 2 * j], f1 = ss[c * 65 + uh + 2 * j + 1];
            float h0 = __half2float(__float2half_rn(f0));
            float h1 = __half2float(__float2half_rn(f1));
            hi[j] = packh2(h0, h1);
            lo[j] = packh2(f0 - h0, f1 - h1);
        }
        uint4* dh = (uint4*)((unsigned*)khi + (size_t)(b * 128 + c) * 2048 + (u0 + uh) / 2);
        uint4* dl = (uint4*)((unsigned*)klo + (size_t)(b * 128 + c) * 2048 + (u0 + uh) / 2);
#pragma unroll
        for (int q = 0; q < 4; q++) {
            dh[q] = make_uint4(hi[4*q], hi[4*q+1], hi[4*q+2], hi[4*q+3]);
            dl[q] = make_uint4(lo[4*q], lo[4*q+1], lo[4*q+2], lo[4*q+3]);
        }
    }
    {   // [u][c] orientation
        int u = t & 63, ch = (t >> 6) * 32;
        unsigned hi[16], lo[16];
#pragma unroll
        for (int j = 0; j < 16; j++) {
            float f0 = ss[(ch + 2 * j) * 65 + u], f1 = ss[(ch + 2 * j + 1) * 65 + u];
            float h0 = __half2float(__float2half_rn(f0));
            float h1 = __half2float(__float2half_rn(f1));
            hi[j] = packh2(h0, h1);
            lo[j] = packh2(f0 - h0, f1 - h1);
        }
        uint4* dh = (uint4*)((unsigned*)kthi + (size_t)(b * 4096 + u0 + u) * 64 + ch / 2);
        uint4* dl = (uint4*)((unsigned*)ktlo + (size_t)(b * 4096 + u0 + u) * 64 + ch / 2);
#pragma unroll
        for (int q = 0; q < 4; q++) {
            dh[q] = make_uint4(hi[4*q], hi[4*q+1], hi[4*q+2], hi[4*q+3]);
            dl[q] = make_uint4(lo[4*q], lo[4*q+1], lo[4*q+2], lo[4*q+3]);
        }
    }
}

// ------------------ transpose + scale + fp16 round: h1 -> h1T[b][w][h][c] ------------------
__global__ void __launch_bounds__(256) transpose_k(const float* __restrict__ h1,
                                                   __half* __restrict__ h1T) {
    __shared__ float sm[128 * 65];
    int h = blockIdx.x, b = blockIdx.y, t = threadIdx.x;
    const float* src = h1 + ((b * 128) * 64 + h) * 64;
    for (int i = 0; i < 32; i++) {
        int idx = t + i * 256;
        int c = idx >> 6, w = idx & 63;
        sm[c * 65 + w] = src[c * 4096 + w] * SCALE_Q;
    }
    __syncthreads();
    unsigned* dst = (unsigned*)h1T;
    for (int i = 0; i < 16; i++) {
        int idx = t + i * 256;                        // 4096 u32
        int w = idx >> 6, cp = idx & 63;
        dst[(size_t)((b * 64 + w) * 64 + h) * 64 + cp] =
            packh2(sm[(2 * cp) * 65 + w], sm[(2 * cp + 1) * 65 + w]);
    }
}

// ------------- transadd: h2[b][c][h][w] = h1 + contrast_embed[aim[b]][c] + oT^T -------------
__global__ void __launch_bounds__(256) transadd_k(const float* __restrict__ h1,
                                                  const float* __restrict__ emb,
                                                  const int* __restrict__ aim,
                                                  const float* __restrict__ oT,
                                                  float* __restrict__ h2) {
    __shared__ float sm[64 * 129];
    int h = blockIdx.x, b = blockIdx.y, t = threadIdx.x;
    int ai = aim[b];
    for (int i = 0; i < 32; i++) {
        int idx = t + i * 256;
        int w = idx >> 7, c = idx & 127;
        sm[w * 129 + c] = oT[((b * 64 + w) * 64 + h) * 128 + c];
    }
    __syncthreads();
    for (int i = 0; i < 32; i++) {
        int idx = t + i * 256;
        int c = idx >> 6, w = idx & 63;
        size_t gi = (size_t)(b * 128 + c) * 4096 + h * 64 + w;
        h2[gi] = h1[gi] + emb[ai * 128 + c] + sm[w * 129 + c];
    }
}

// ------------------------- mma.sync attention (fp16, 2 MMAs/product) -------------------------
// u32-unit offsets
#define OFF_AH   0                       /* [128m][68] */
#define OFF_KTH  (OFF_AH + 128 * 68)     /* [64u][68]  */
#define OFF_KTL  (OFF_KTH + 64 * 68)
#define OFF_KCH  (OFF_KTL + 64 * 68)     /* [128c][36] */
#define OFF_KCL  (OFF_KCH + 128 * 36)
#define OFF_SST  (OFF_KCL + 128 * 36)    /* f32 [64u][129] */
#define OFF_PH   (OFF_SST + 64 * 129)    /* [128m][36] */
#define OFF_REDS (OFF_PH + 128 * 36)
#define OFF_RSM  (OFF_REDS + 256)
#define ATTN_SMEM ((OFF_RSM + 128) * 4)

__global__ void __launch_bounds__(256, 1) attn_mma_k(const __half* __restrict__ h1T,
        const __half* __restrict__ khi, const __half* __restrict__ klo,
        const __half* __restrict__ kthi, const __half* __restrict__ ktlo,
        float* __restrict__ oT) {
    extern __shared__ __align__(16) unsigned sma[];
    unsigned* Ah   = sma + OFF_AH;
    unsigned* KTh  = sma + OFF_KTH;
    unsigned* KTl  = sma + OFF_KTL;
    unsigned* Kch  = sma + OFF_KCH;
    unsigned* Kcl  = sma + OFF_KCL;
    float*    SsT  = (float*)(sma + OFF_SST);
    unsigned* Ph   = sma + OFF_PH;
    float*    reds = (float*)(sma + OFF_REDS);
    float*    rsm  = (float*)(sma + OFF_RSM);

    int t = threadIdx.x, lane = t & 31, wid = t >> 5;
    int wp = blockIdx.x, b = blockIdx.y;
    int g = lane >> 2, tq = lane & 3;
    int mrow = wid * 16;

    // A tile (128 rows = 2w x 64h), fp16 raw copy
#pragma unroll
    for (int i = 0; i < 8; i++) {
        int idx = t + i * 256;                        // 2048 uint4
        int m = idx >> 4, q = idx & 15;
        *(uint4*)(Ah + m * 68 + q * 4) =
            ((const uint4*)h1T)[(size_t)((b * 64 + 2 * wp + (m >> 6)) * 64 + (m & 63)) * 16 + q];
    }

    float o[16][4];
#pragma unroll
    for (int n = 0; n < 16; n++)
#pragma unroll
        for (int k = 0; k < 4; k++) o[n][k] = 0.f;

    for (int tile = 0; tile < 64; tile++) {
        int u0 = tile * 64;
        __syncthreads();
        // K tiles: KT [64u][128c] hi/lo, Kc [128c][64u] hi/lo
#pragma unroll
        for (int i = 0; i < 4; i++) {
            int idx = t + i * 256;
            {
                int u = idx >> 4, q = idx & 15;
                size_t gi = (size_t)(b * 4096 + u0 + u) * 16 + q;
                *(uint4*)(KTh + u * 68 + q * 4) = ((const uint4*)kthi)[gi];
                *(uint4*)(KTl + u * 68 + q * 4) = ((const uint4*)ktlo)[gi];
            }
            {
                int c = idx >> 3, q = idx & 7;
                size_t gi = (size_t)(b * 128 + c) * 512 + tile * 8 + q;
                *(uint4*)(Kch + c * 36 + q * 4) = ((const uint4*)khi)[gi];
                *(uint4*)(Kcl + c * 36 + q * 4) = ((const uint4*)klo)[gi];
            }
        }
        __syncthreads();

        // GEMM1: S(128m x 64u) = Ah * (KTh + KTl)
        float s[8][4];
#pragma unroll
        for (int n = 0; n < 8; n++)
#pragma unroll
            for (int k = 0; k < 4; k++) s[n][k] = 0.f;
#pragma unroll
        for (int ks = 0; ks < 8; ks++) {
            int r0 = (mrow + g) * 68 + 8 * ks + tq;
            int r1 = r0 + 8 * 68;
            unsigned a0 = Ah[r0], a1 = Ah[r1], a2 = Ah[r0 + 4], a3 = Ah[r1 + 4];
#pragma unroll
            for (int n = 0; n < 8; n++) {
                int bi = (8 * n + g) * 68 + 8 * ks + tq;
                unsigned bh0 = KTh[bi], bh1 = KTh[bi + 4];
                unsigned bl0 = KTl[bi], bl1 = KTl[bi + 4];
                mma_h(s[n], a0, a1, a2, a3, bh0, bh1);
                mma_h(s[n], a0, a1, a2, a3, bl0, bl1);
            }
        }
#pragma unroll
        for (int n = 0; n < 8; n++) {
            int ub = 8 * n + 2 * tq;
            SsT[ub * 129 + mrow + g]           = s[n][0];
            SsT[(ub + 1) * 129 + mrow + g]     = s[n][1];
            SsT[ub * 129 + mrow + g + 8]       = s[n][2];
            SsT[(ub + 1) * 129 + mrow + g + 8] = s[n][3];
        }
        __syncthreads();

        // exp (no max-sub) + per-w-half column sums
        {
            int u = t & 63, qq = t >> 6;
            float* col = SsT + u * 129 + qq * 32;
            float ps = 0.f;
#pragma unroll
            for (int j = 0; j < 32; j++) {
                float e = __expf(col[j]);
                col[j] = e;
                ps += e;
            }
            reds[qq * 64 + u] = ps;
        }
        __syncthreads();
        if (t < 128) {
            int half = t >> 6, u = t & 63;
            rsm[half * 64 + u] = 1.f / (reds[2 * half * 64 + u] + reds[(2 * half + 1) * 64 + u]);
        }
        __syncthreads();

        // P = E * rs -> fp16 round -> Ph [m][u]
        {
            int m = t >> 1, uh = (t & 1) * 32, half = m >> 6;
            const float* rp = rsm + half * 64;
            unsigned* ph = Ph + m * 36 + (uh >> 1);
#pragma unroll
            for (int j = 0; j < 16; j++) {
                int u = uh + 2 * j;
                ph[j] = packh2(SsT[u * 129 + m] * rp[u],
                               SsT[(u + 1) * 129 + m] * rp[u + 1]);
            }
        }
        __syncthreads();

        // GEMM2: O(128m x 128c) += Ph * (Kch + Kcl)
#pragma unroll
        for (int ks = 0; ks < 4; ks++) {
            int r0 = (mrow + g) * 36 + 8 * ks + tq;
            int r1 = r0 + 8 * 36;
            unsigned p0 = Ph[r0], p1 = Ph[r1], p2 = Ph[r0 + 4], p3 = Ph[r1 + 4];
#pragma unroll
            for (int n = 0; n < 16; n++) {
                int bi = (8 * n + g) * 36 + 8 * ks + tq;
                unsigned bh0 = Kch[bi], bh1 = Kch[bi + 4];
                unsigned bl0 = Kcl[bi], bl1 = Kcl[bi + 4];
                mma_h(o[n], p0, p1, p2, p3, bh0, bh1);
                mma_h(o[n], p0, p1, p2, p3, bl0, bl1);
            }
        }
    }

    // epilogue: O -> oT[b][w][h][c]
    {
        size_t base = (size_t)(b * 64 + 2 * wp + (mrow >> 6)) * 64;
        int hrow = (mrow & 63) + g;
        float* r0 = oT + (base + hrow) * 128;
        float* r1 = oT + (base + hrow + 8) * 128;
#pragma unroll
        for (int n = 0; n < 16; n++) {
            *(float2*)(r0 + 8 * n + 2 * tq) = make_float2(o[n][0], o[n][1]);
            *(float2*)(r1 + 8 * n + 2 * tq) = make_float2(o[n][2], o[n][3]);
        }
    }
}

// ------------------------- launch -------------------------
extern "C" void kernel_launch(void* const* d_in, const int* in_sizes, int n_in,
                              void* d_out, int out_size) {
    const float* x    = (const float*)d_in[0];
    const float* tt   = (const float*)d_in[1];
    const int*   aim  = (const int*)d_in[2];
    const float* cond = (const float*)d_in[3];
    const float* g1s  = (const float*)d_in[4];
    const float* g1b  = (const float*)d_in[5];
    const float* c1w  = (const float*)d_in[6];
    const float* c1b  = (const float*)d_in[7];
    const float* mw   = (const float*)d_in[8];
    const float* mb   = (const float*)d_in[9];
    const float* cw   = (const float*)d_in[10];
    const float* cbi  = (const float*)d_in[11];
    const float* g2s  = (const float*)d_in[12];
    const float* g2b  = (const float*)d_in[13];
    const float* c2w  = (const float*)d_in[14];
    const float* c2b  = (const float*)d_in[15];
    const float* emb  = (const float*)d_in[16];
    float* out = (float*)d_out;

    float *h1, *h2, *oT, *temb, *mean, *rstd;
    __half *h1T, *khi, *klo, *kthi, *ktlo, *athi, *atlo, *wh;
    cudaGetSymbolAddress((void**)&h1,   g_h1);
    cudaGetSymbolAddress((void**)&h2,   g_h2);
    cudaGetSymbolAddress((void**)&oT,   g_oT);
    cudaGetSymbolAddress((void**)&temb, g_temb);
    cudaGetSymbolAddress((void**)&mean, g_mean);
    cudaGetSymbolAddress((void**)&rstd, g_rstd);
    cudaGetSymbolAddress((void**)&h1T,  g_h1T);
    cudaGetSymbolAddress((void**)&khi,  g_khi);
    cudaGetSymbolAddress((void**)&klo,  g_klo);
    cudaGetSymbolAddress((void**)&kthi, g_kthi);
    cudaGetSymbolAddress((void**)&ktlo, g_ktlo);
    cudaGetSymbolAddress((void**)&athi, g_athi);
    cudaGetSymbolAddress((void**)&atlo, g_atlo);
    cudaGetSymbolAddress((void**)&wh,   g_wh);

    cudaFuncSetAttribute(attn_mma_k, cudaFuncAttributeMaxDynamicSharedMemorySize, ATTN_SMEM);
    cudaFuncSetAttribute(conv_mma_k<0>, cudaFuncAttributeMaxDynamicSharedMemorySize, CONV_SMEM);
    cudaFuncSetAttribute(conv_mma_k<1>, cudaFuncAttributeMaxDynamicSharedMemorySize, CONV_SMEM);
    cudaFuncSetAttribute(cond1x1s_k, cudaFuncAttributeMaxDynamicSharedMemorySize, COND_SMEM);

    gn_stats_k<<<128, 256>>>(x, mean, rstd);
    gnact_k<<<dim3(64, 4), 256>>>(x, mean, rstd, g1s, g1b, athi, atlo);
    wround_k<<<576, 256>>>(c1w, wh);
    temb_k<<<4, 128>>>(tt, mw, mb, temb);
    conv_mma_k<0><<<dim3(64, 4), 256, CONV_SMEM>>>(athi, atlo, wh, c1b, temb, nullptr, h1);
    cond1x1s_k<<<dim3(64, 4), 256, COND_SMEM>>>(cond, cw, cbi, khi, klo, kthi, ktlo);
    transpose_k<<<dim3(64, 4), 256>>>(h1, h1T);
    attn_mma_k<<<dim3(32, 4), 256, ATTN_SMEM>>>(h1T, khi, klo, kthi, ktlo, oT);
    transadd_k<<<dim3(64, 4), 256>>>(h1, emb, aim, oT, h2);
    gn_stats_k<<<128, 256>>>(h2, mean, rstd);
    gnact_k<<<dim3(64, 4), 256>>>(h2, mean, rstd, g2s, g2b, athi, atlo);
    wround_k<<<576, 256>>>(c2w, wh);
    conv_mma_k<1><<<dim3(64, 4), 256, CONV_SMEM>>>(athi, atlo, wh, c2b, nullptr, x, out);
}

// round 14
// speedup vs baseline: 3.1452x; 1.1882x over previous
#include <cuda_runtime.h>
#include <cuda_fp16.h>
#include <math.h>
#include <stdint.h>

typedef unsigned long long ull;

#define NB 4
#define NC 128
#define NHW 4096
#define NG 32
#define NTD 512
#define SCALE_Q 0.088388347648318447f  /* 1/sqrt(128) */

// ------------------------- static scratch (no allocations) -------------------------
static __device__ float  g_h1  [NB * NC * NHW];
static __device__ float  g_h2  [NB * NC * NHW];
static __device__ float  g_oT  [NB * NHW * NC];   // attn out [b][w][h][c]
static __device__ float  g_temb[NB * NC];
static __device__ float  g_mean[NB * NG];
static __device__ float  g_rstd[NB * NG];
static __device__ __half g_h1T [NB * NHW * NC];   // [b][w][h][c] * 1/sqrt(C), fp16
static __device__ __half g_khi [NB * NC * NHW];   // K [b][c][u] hi
static __device__ __half g_kthi[NB * NHW * NC];   // K [b][u][c] hi
static __device__ __half g_ktlo[NB * NHW * NC];   // K [b][u][c] lo
static __device__ __half g_athi[NB * NHW * NC];   // act [b][h][w][c] hi
static __device__ __half g_atlo[NB * NHW * NC];   // act [b][h][w][c] lo
static __device__ __half g_wh  [3 * 128 * 384];   // weights [kh][co][kw*128+ci] (fp16 round)

// ------------------------- helpers -------------------------
__device__ __forceinline__ void fma2(ull& d, ull a, ull b) {
    asm("fma.rn.f32x2 %0, %1, %2, %0;" : "+l"(d) : "l"(a), "l"(b));
}
__device__ __forceinline__ ull dup2(float x) {
    ull r;
    asm("mov.b64 %0, {%1, %2};" : "=l"(r) : "f"(x), "f"(x));
    return r;
}
__device__ __forceinline__ float2 unp2(ull v) {
    float2 r;
    asm("mov.b64 {%0, %1}, %2;" : "=f"(r.x), "=f"(r.y) : "l"(v));
    return r;
}
__device__ __forceinline__ float siluf(float x) { return x / (1.0f + __expf(-x)); }

__device__ __forceinline__ unsigned packh2(float a, float b) {
    __half2 t = __floats2half2_rn(a, b);
    return *reinterpret_cast<unsigned*>(&t);
}

// fp16 HMMA m16n8k16 (family-safe PTX, f32 accum)
__device__ __forceinline__ void mma_h(float* d, unsigned a0, unsigned a1,
                                      unsigned a2, unsigned a3,
                                      unsigned b0, unsigned b1) {
    asm volatile(
        "mma.sync.aligned.m16n8k16.row.col.f32.f16.f16.f32 "
        "{%0,%1,%2,%3}, {%4,%5,%6,%7}, {%8,%9}, {%0,%1,%2,%3};"
        : "+f"(d[0]), "+f"(d[1]), "+f"(d[2]), "+f"(d[3])
        : "r"(a0), "r"(a1), "r"(a2), "r"(a3), "r"(b0), "r"(b1));
}

// ------------------------- group-norm statistics -------------------------
__global__ void __launch_bounds__(256) gn_stats_k(const float* __restrict__ src,
                                                  float* __restrict__ mean,
                                                  float* __restrict__ rstd) {
    int bg = blockIdx.x;
    const float4* p = (const float4*)(src + bg * 16384);
    float s = 0.f, ss = 0.f;
    for (int i = threadIdx.x; i < 4096; i += 256) {
        float4 v = p[i];
        s  += v.x + v.y + v.z + v.w;
        ss += v.x * v.x + v.y * v.y + v.z * v.z + v.w * v.w;
    }
    for (int off = 16; off; off >>= 1) {
        s  += __shfl_down_sync(0xffffffffu, s,  off);
        ss += __shfl_down_sync(0xffffffffu, ss, off);
    }
    __shared__ float ws[8], wss[8];
    int wid = threadIdx.x >> 5, lane = threadIdx.x & 31;
    if (lane == 0) { ws[wid] = s; wss[wid] = ss; }
    __syncthreads();
    if (threadIdx.x == 0) {
        float ts = 0.f, tss = 0.f;
        for (int i = 0; i < 8; i++) { ts += ws[i]; tss += wss[i]; }
        float m = ts * (1.f / 16384.f);
        float var = tss * (1.f / 16384.f) - m * m;
        mean[bg] = m;
        rstd[bg] = rsqrtf(var + 1e-5f);
    }
}

// ------------- GN + SiLU + transpose + fp16 split: src[b][c][h][w] -> at{hi,lo}[b][h][w][c] ---
__global__ void __launch_bounds__(256) gnact_k(const float* __restrict__ src,
                                               const float* __restrict__ mean,
                                               const float* __restrict__ rstd,
                                               const float* __restrict__ sc,
                                               const float* __restrict__ bi,
                                               __half* __restrict__ athi,
                                               __half* __restrict__ atlo) {
    __shared__ float smt[128 * 65];
    __shared__ float a_s[128], b_s[128];
    int h = blockIdx.x, b = blockIdx.y, t = threadIdx.x;
    if (t < 128) {
        float a = rstd[b * 32 + (t >> 2)] * sc[t];
        a_s[t] = a;
        b_s[t] = bi[t] - mean[b * 32 + (t >> 2)] * a;
    }
    __syncthreads();
    for (int i = 0; i < 32; i++) {
        int idx = t + i * 256;
        int c = idx >> 6, w = idx & 63;
        float v = src[(b * 128 + c) * 4096 + h * 64 + w];
        smt[c * 65 + w] = siluf(v * a_s[c] + b_s[c]);
    }
    __syncthreads();
    unsigned* oh = (unsigned*)(athi + (size_t)(b * 64 + h) * 64 * 128);
    unsigned* ol = (unsigned*)(atlo + (size_t)(b * 64 + h) * 64 * 128);
    for (int i = 0; i < 16; i++) {
        int idx = t + i * 256;                        // 4096 u32
        int w = idx >> 6, cp = idx & 63;
        float f0 = smt[(2 * cp) * 65 + w], f1 = smt[(2 * cp + 1) * 65 + w];
        float h0 = __half2float(__float2half_rn(f0));
        float h1 = __half2float(__float2half_rn(f1));
        oh[w * 64 + cp] = packh2(h0, h1);
        ol[w * 64 + cp] = packh2(f0 - h0, f1 - h1);
    }
}

// ------------------------- weight reorder + fp16 round -------------------------
__global__ void __launch_bounds__(256) wround_k(const float* __restrict__ wgt,
                                                __half* __restrict__ wh) {
    int o = blockIdx.x * 256 + threadIdx.x;          // 147456 outputs
    int kh = o / 49152, r = o % 49152;
    int co = r / 384,  r2 = r % 384;
    int kw = r2 >> 7,  ci = r2 & 127;
    wh[o] = __float2half_rn(wgt[((co * 128 + ci) * 3 + kh) * 3 + kw]);
}

// ------------------------- time embedding: warp per co -------------------------
__global__ void __launch_bounds__(256) temb_k(const float* __restrict__ t,
                                              const float* __restrict__ mw,
                                              const float* __restrict__ mb,
                                              float* __restrict__ temb) {
    __shared__ float st[NTD];
    int b = blockIdx.y, tid = threadIdx.x;
    int lane = tid & 31, wid = tid >> 5;
    for (int k = tid; k < NTD; k += 256) st[k] = siluf(t[b * NTD + k]);
    __syncthreads();
    int co = blockIdx.x * 8 + wid;
    const float* wr = mw + co * NTD;
    float acc = 0.f;
#pragma unroll
    for (int j = 0; j < 16; j++) {
        int k = lane + 32 * j;
        acc += st[k] * wr[k];
    }
    for (int off = 16; off; off >>= 1)
        acc += __shfl_down_sync(0xffffffffu, acc, off);
    if (lane == 0) temb[b * NC + co] = acc + mb[co];
}

// ------------------------- tensor-core 3x3 conv -------------------------
#define CV_WH 0
#define CV_XH (128 * 68)
#define CV_XL (128 * 68 + 64 * 68)
#define CONV_SMEM ((128 * 68 + 2 * 64 * 68) * 4)

template <int MODE>
__global__ void __launch_bounds__(256, 2) conv_mma_k(
        const __half* __restrict__ athi, const __half* __restrict__ atlo,
        const __half* __restrict__ wh,
        const float* __restrict__ bias, const float* __restrict__ temb,
        const float* __restrict__ resid, float* __restrict__ dst) {
    extern __shared__ __align__(16) unsigned smc[];
    unsigned* Wh = smc + CV_WH;
    unsigned* Xh = smc + CV_XH;
    unsigned* Xl = smc + CV_XL;
    int t = threadIdx.x, lane = t & 31, wid = t >> 5;
    int h = blockIdx.x, b = blockIdx.y;
    int g = lane >> 2, tq = lane & 3;
    int mrow = wid * 16;

    float o[8][4];
#pragma unroll
    for (int n = 0; n < 8; n++)
#pragma unroll
        for (int k = 0; k < 4; k++) o[n][k] = 0.f;

    for (int tap = 0; tap < 9; tap++) {
        int kh = tap / 3, kw = tap % 3;
        int hh = h + kh - 1;
        if (hh < 0 || hh > 63) continue;
        __syncthreads();
#pragma unroll
        for (int i = 0; i < 4; i++) {
            int idx = t + i * 256;
            int w = idx >> 4, q = idx & 15;
            int ws = w + kw - 1;
            uint4 vh = make_uint4(0, 0, 0, 0), vl = make_uint4(0, 0, 0, 0);
            if (ws >= 0 && ws < 64) {
                size_t gi = (size_t)((b * 64 + hh) * 64 + ws) * 16 + q;
                vh = ((const uint4*)athi)[gi];
                vl = ((const uint4*)atlo)[gi];
            }
            *(uint4*)(Xh + w * 68 + q * 4) = vh;
            *(uint4*)(Xl + w * 68 + q * 4) = vl;
        }
#pragma unroll
        for (int i = 0; i < 8; i++) {
            int idx = t + i * 256;
            int co = idx >> 4, q = idx & 15;
            *(uint4*)(Wh + co * 68 + q * 4) =
                ((const uint4*)wh)[(size_t)(kh * 128 + co) * 48 + kw * 16 + q];
        }
        __syncthreads();
#pragma unroll
        for (int ks = 0; ks < 8; ks++) {
            int r0 = (mrow + g) * 68 + 8 * ks + tq, r1 = r0 + 8 * 68;
            unsigned a0 = Wh[r0], a1 = Wh[r1], a2 = Wh[r0 + 4], a3 = Wh[r1 + 4];
#pragma unroll
            for (int n = 0; n < 8; n++) {
                int bi = (8 * n + g) * 68 + 8 * ks + tq;
                unsigned xh0 = Xh[bi], xh1 = Xh[bi + 4];
                unsigned xl0 = Xl[bi], xl1 = Xl[bi + 4];
                mma_h(o[n], a0, a1, a2, a3, xh0, xh1);
                mma_h(o[n], a0, a1, a2, a3, xl0, xl1);
            }
        }
    }
    int co0 = mrow + g;
    float add0 = bias[co0]     + (MODE == 0 ? temb[b * 128 + co0]     : 0.f);
    float add1 = bias[co0 + 8] + (MODE == 0 ? temb[b * 128 + co0 + 8] : 0.f);
#pragma unroll
    for (int n = 0; n < 8; n++) {
        int w = 8 * n + 2 * tq;
        size_t i0 = ((size_t)(b * 128 + co0) * 64 + h) * 64 + w;
        size_t i1 = i0 + 8 * 4096;
        float v00 = o[n][0] + add0, v01 = o[n][1] + add0;
        float v10 = o[n][2] + add1, v11 = o[n][3] + add1;
        if (MODE == 1) {
            v00 += resid[i0]; v01 += resid[i0 + 1];
            v10 += resid[i1]; v11 += resid[i1 + 1];
        }
        *(float2*)(dst + i0) = make_float2(v00, v01);
        *(float2*)(dst + i1) = make_float2(v10, v11);
    }
}

// --------------- cond 1x1 projection + fp16 split (K: hi [c][u]; hi+lo [u][c]) ---------------
#define COND_SMEM ((128 * 64 + 128 * 65) * 4)
__global__ void __launch_bounds__(256) cond1x1s_k(const float* __restrict__ cond,
                                                  const float* __restrict__ wt,
                                                  const float* __restrict__ bias,
                                                  __half* __restrict__ khi,
                                                  __half* __restrict__ kthi,
                                                  __half* __restrict__ ktlo) {
    extern __shared__ __align__(16) float smf[];
    float* ct = smf;                 // [128ci][64u]
    float* ss = smf + 128 * 64;      // [128co][65]
    int u0 = blockIdx.x * 64, b = blockIdx.y, t = threadIdx.x;
    for (int i = 0; i < 32; i++) {
        int idx = t + i * 256;
        ct[idx] = cond[(b * 128 + (idx >> 6)) * 4096 + u0 + (idx & 63)];
    }
    __syncthreads();
    {
        int co = t & 127, uh = t >> 7;
        ull acc[16];
#pragma unroll
        for (int j = 0; j < 16; j++) acc[j] = 0ull;
        const float* wrow = wt + co * 128;
        for (int ci = 0; ci < 128; ci++) {
            ull wv = dup2(__ldg(wrow + ci));
            const ull* kr = (const ull*)&ct[ci * 64 + uh * 32];
#pragma unroll
            for (int j = 0; j < 16; j++) fma2(acc[j], wv, kr[j]);
        }
        float bv = bias[co];
        float* op = ss + co * 65 + uh * 32;
#pragma unroll
        for (int j = 0; j < 16; j++) {
            float2 v = unp2(acc[j]);
            op[2 * j]     = v.x + bv;
            op[2 * j + 1] = v.y + bv;
        }
    }
    __syncthreads();
    {   // [c][u] orientation, hi only
        int c = t >> 1, uh = (t & 1) * 32;
        unsigned hi[16];
#pragma unroll
        for (int j = 0; j < 16; j++) {
            float f0 = ss[c * 65 + uh + 2 * j], f1 = ss[c * 65 + uh + 2 * j + 1];
            hi[j] = packh2(__half2float(__float2half_rn(f0)),
                           __half2float(__float2half_rn(f1)));
        }
        uint4* dh = (uint4*)((unsigned*)khi + (size_t)(b * 128 + c) * 2048 + (u0 + uh) / 2);
#pragma unroll
        for (int q = 0; q < 4; q++)
            dh[q] = make_uint4(hi[4*q], hi[4*q+1], hi[4*q+2], hi[4*q+3]);
    }
    {   // [u][c] orientation, hi + lo
        int u = t & 63, ch = (t >> 6) * 32;
        unsigned hi[16], lo[16];
#pragma unroll
        for (int j = 0; j < 16; j++) {
            float f0 = ss[(ch + 2 * j) * 65 + u], f1 = ss[(ch + 2 * j + 1) * 65 + u];
            float h0 = __half2float(__float2half_rn(f0));
            float h1 = __half2float(__float2half_rn(f1));
            hi[j] = packh2(h0, h1);
            lo[j] = packh2(f0 - h0, f1 - h1);
        }
        uint4* dh = (uint4*)((unsigned*)kthi + (size_t)(b * 4096 + u0 + u) * 64 + ch / 2);
        uint4* dl = (uint4*)((unsigned*)ktlo + (size_t)(b * 4096 + u0 + u) * 64 + ch / 2);
#pragma unroll
        for (int q = 0; q < 4; q++) {
            dh[q] = make_uint4(hi[4*q], hi[4*q+1], hi[4*q+2], hi[4*q+3]);
            dl[q] = make_uint4(lo[4*q], lo[4*q+1], lo[4*q+2], lo[4*q+3]);
        }
    }
}

// ------------------ transpose + scale + fp16 round: h1 -> h1T[b][w][h][c] ------------------
__global__ void __launch_bounds__(256) transpose_k(const float* __restrict__ h1,
                                                   __half* __restrict__ h1T) {
    __shared__ float sm[128 * 65];
    int h = blockIdx.x, b = blockIdx.y, t = threadIdx.x;
    const float* src = h1 + ((b * 128) * 64 + h) * 64;
    for (int i = 0; i < 32; i++) {
        int idx = t + i * 256;
        int c = idx >> 6, w = idx & 63;
        sm[c * 65 + w] = src[c * 4096 + w] * SCALE_Q;
    }
    __syncthreads();
    unsigned* dst = (unsigned*)h1T;
    for (int i = 0; i < 16; i++) {
        int idx = t + i * 256;
        int w = idx >> 6, cp = idx & 63;
        dst[(size_t)((b * 64 + w) * 64 + h) * 64 + cp] =
            packh2(sm[(2 * cp) * 65 + w], sm[(2 * cp + 1) * 65 + w]);
    }
}

// ------------- transadd: h2 = h1 + contrast_embed[aim[b]][c] + oT^T -------------
__global__ void __launch_bounds__(256) transadd_k(const float* __restrict__ h1,
                                                  const float* __restrict__ emb,
                                                  const int* __restrict__ aim,
                                                  const float* __restrict__ oT,
                                                  float* __restrict__ h2) {
    __shared__ float sm[64 * 129];
    int h = blockIdx.x, b = blockIdx.y, t = threadIdx.x;
    int ai = aim[b];
    for (int i = 0; i < 32; i++) {
        int idx = t + i * 256;
        int w = idx >> 7, c = idx & 127;
        sm[w * 129 + c] = oT[((b * 64 + w) * 64 + h) * 128 + c];
    }
    __syncthreads();
    for (int i = 0; i < 32; i++) {
        int idx = t + i * 256;
        int c = idx >> 6, w = idx & 63;
        size_t gi = (size_t)(b * 128 + c) * 4096 + h * 64 + w;
        h2[gi] = h1[gi] + emb[ai * 128 + c] + sm[w * 129 + c];
    }
}

// ------------------------- mma.sync attention (fp16; GEMM2 single-term K) ---------------
#define OFF_AH   0                       /* [128m][68] */
#define OFF_KTH  (OFF_AH + 128 * 68)     /* [64u][68]  */
#define OFF_KTL  (OFF_KTH + 64 * 68)
#define OFF_KCH  (OFF_KTL + 64 * 68)     /* [128c][36] */
#define OFF_SST  (OFF_KCH + 128 * 36)    /* f32 [64u][129] */
#define OFF_PH   (OFF_SST + 64 * 129)    /* [128m][36] */
#define OFF_REDS (OFF_PH + 128 * 36)
#define OFF_RSM  (OFF_REDS + 256)
#define ATTN_SMEM ((OFF_RSM + 128) * 4)

__global__ void __launch_bounds__(256, 1) attn_mma_k(const __half* __restrict__ h1T,
        const __half* __restrict__ khi,
        const __half* __restrict__ kthi, const __half* __restrict__ ktlo,
        float* __restrict__ oT) {
    extern __shared__ __align__(16) unsigned sma[];
    unsigned* Ah   = sma + OFF_AH;
    unsigned* KTh  = sma + OFF_KTH;
    unsigned* KTl  = sma + OFF_KTL;
    unsigned* Kch  = sma + OFF_KCH;
    float*    SsT  = (float*)(sma + OFF_SST);
    unsigned* Ph   = sma + OFF_PH;
    float*    reds = (float*)(sma + OFF_REDS);
    float*    rsm  = (float*)(sma + OFF_RSM);

    int t = threadIdx.x, lane = t & 31, wid = t >> 5;
    int wp = blockIdx.x, b = blockIdx.y;
    int g = lane >> 2, tq = lane & 3;
    int mrow = wid * 16;

#pragma unroll
    for (int i = 0; i < 8; i++) {
        int idx = t + i * 256;
        int m = idx >> 4, q = idx & 15;
        *(uint4*)(Ah + m * 68 + q * 4) =
            ((const uint4*)h1T)[(size_t)((b * 64 + 2 * wp + (m >> 6)) * 64 + (m & 63)) * 16 + q];
    }

    float o[16][4];
#pragma unroll
    for (int n = 0; n < 16; n++)
#pragma unroll
        for (int k = 0; k < 4; k++) o[n][k] = 0.f;

    for (int tile = 0; tile < 64; tile++) {
        int u0 = tile * 64;
        __syncthreads();
#pragma unroll
        for (int i = 0; i < 4; i++) {
            int idx = t + i * 256;
            {
                int u = idx >> 4, q = idx & 15;
                size_t gi = (size_t)(b * 4096 + u0 + u) * 16 + q;
                *(uint4*)(KTh + u * 68 + q * 4) = ((const uint4*)kthi)[gi];
                *(uint4*)(KTl + u * 68 + q * 4) = ((const uint4*)ktlo)[gi];
            }
            {
                int c = idx >> 3, q = idx & 7;
                *(uint4*)(Kch + c * 36 + q * 4) =
                    ((const uint4*)khi)[(size_t)(b * 128 + c) * 512 + tile * 8 + q];
            }
        }
        __syncthreads();

        // GEMM1: S = Ah * (KTh + KTl)
        float s[8][4];
#pragma unroll
        for (int n = 0; n < 8; n++)
#pragma unroll
            for (int k = 0; k < 4; k++) s[n][k] = 0.f;
#pragma unroll
        for (int ks = 0; ks < 8; ks++) {
            int r0 = (mrow + g) * 68 + 8 * ks + tq;
            int r1 = r0 + 8 * 68;
            unsigned a0 = Ah[r0], a1 = Ah[r1], a2 = Ah[r0 + 4], a3 = Ah[r1 + 4];
#pragma unroll
            for (int n = 0; n < 8; n++) {
                int bi = (8 * n + g) * 68 + 8 * ks + tq;
                unsigned bh0 = KTh[bi], bh1 = KTh[bi + 4];
                unsigned bl0 = KTl[bi], bl1 = KTl[bi + 4];
                mma_h(s[n], a0, a1, a2, a3, bh0, bh1);
                mma_h(s[n], a0, a1, a2, a3, bl0, bl1);
            }
        }
#pragma unroll
        for (int n = 0; n < 8; n++) {
            int ub = 8 * n + 2 * tq;
            SsT[ub * 129 + mrow + g]           = s[n][0];
            SsT[(ub + 1) * 129 + mrow + g]     = s[n][1];
            SsT[ub * 129 + mrow + g + 8]       = s[n][2];
            SsT[(ub + 1) * 129 + mrow + g + 8] = s[n][3];
        }
        __syncthreads();

        // exp (no max-sub) + per-w-half column sums
        {
            int u = t & 63, qq = t >> 6;
            float* col = SsT + u * 129 + qq * 32;
            float ps = 0.f;
#pragma unroll
            for (int j = 0; j < 32; j++) {
                float e = __expf(col[j]);
                col[j] = e;
                ps += e;
            }
            reds[qq * 64 + u] = ps;
        }
        __syncthreads();
        if (t < 128) {
            int half = t >> 6, u = t & 63;
            rsm[half * 64 + u] = 1.f / (reds[2 * half * 64 + u] + reds[(2 * half + 1) * 64 + u]);
        }
        __syncthreads();

        // P = E * rs -> fp16 round
        {
            int m = t >> 1, uh = (t & 1) * 32, half = m >> 6;
            const float* rp = rsm + half * 64;
            unsigned* ph = Ph + m * 36 + (uh >> 1);
#pragma unroll
            for (int j = 0; j < 16; j++) {
                int u = uh + 2 * j;
                ph[j] = packh2(SsT[u * 129 + m] * rp[u],
                               SsT[(u + 1) * 129 + m] * rp[u + 1]);
            }
        }
        __syncthreads();

        // GEMM2: O += Ph * Kch (single-term K)
#pragma unroll
        for (int ks = 0; ks < 4; ks++) {
            int r0 = (mrow + g) * 36 + 8 * ks + tq;
            int r1 = r0 + 8 * 36;
            unsigned p0 = Ph[r0], p1 = Ph[r1], p2 = Ph[r0 + 4], p3 = Ph[r1 + 4];
#pragma unroll
            for (int n = 0; n < 16; n++) {
                int bi = (8 * n + g) * 36 + 8 * ks + tq;
                mma_h(o[n], p0, p1, p2, p3, Kch[bi], Kch[bi + 4]);
            }
        }
    }

    {
        size_t base = (size_t)(b * 64 + 2 * wp + (mrow >> 6)) * 64;
        int hrow = (mrow & 63) + g;
        float* r0 = oT + (base + hrow) * 128;
        float* r1 = oT + (base + hrow + 8) * 128;
#pragma unroll
        for (int n = 0; n < 16; n++) {
            *(float2*)(r0 + 8 * n + 2 * tq) = make_float2(o[n][0], o[n][1]);
            *(float2*)(r1 + 8 * n + 2 * tq) = make_float2(o[n][2], o[n][3]);
        }
    }
}

// ------------------------- launch -------------------------
extern "C" void kernel_launch(void* const* d_in, const int* in_sizes, int n_in,
                              void* d_out, int out_size) {
    const float* x    = (const float*)d_in[0];
    const float* tt   = (const float*)d_in[1];
    const int*   aim  = (const int*)d_in[2];
    const float* cond = (const float*)d_in[3];
    const float* g1s  = (const float*)d_in[4];
    const float* g1b  = (const float*)d_in[5];
    const float* c1w  = (const float*)d_in[6];
    const float* c1b  = (const float*)d_in[7];
    const float* mw   = (const float*)d_in[8];
    const float* mb   = (const float*)d_in[9];
    const float* cw   = (const float*)d_in[10];
    const float* cbi  = (const float*)d_in[11];
    const float* g2s  = (const float*)d_in[12];
    const float* g2b  = (const float*)d_in[13];
    const float* c2w  = (const float*)d_in[14];
    const float* c2b  = (const float*)d_in[15];
    const float* emb  = (const float*)d_in[16];
    float* out = (float*)d_out;

    float *h1, *h2, *oT, *temb, *mean, *rstd;
    __half *h1T, *khi, *kthi, *ktlo, *athi, *atlo, *wh;
    cudaGetSymbolAddress((void**)&h1,   g_h1);
    cudaGetSymbolAddress((void**)&h2,   g_h2);
    cudaGetSymbolAddress((void**)&oT,   g_oT);
    cudaGetSymbolAddress((void**)&temb, g_temb);
    cudaGetSymbolAddress((void**)&mean, g_mean);
    cudaGetSymbolAddress((void**)&rstd, g_rstd);
    cudaGetSymbolAddress((void**)&h1T,  g_h1T);
    cudaGetSymbolAddress((void**)&khi,  g_khi);
    cudaGetSymbolAddress((void**)&kthi, g_kthi);
    cudaGetSymbolAddress((void**)&ktlo, g_ktlo);
    cudaGetSymbolAddress((void**)&athi, g_athi);
    cudaGetSymbolAddress((void**)&atlo, g_atlo);
    cudaGetSymbolAddress((void**)&wh,   g_wh);

    cudaFuncSetAttribute(attn_mma_k, cudaFuncAttributeMaxDynamicSharedMemorySize, ATTN_SMEM);
    cudaFuncSetAttribute(conv_mma_k<0>, cudaFuncAttributeMaxDynamicSharedMemorySize, CONV_SMEM);
    cudaFuncSetAttribute(conv_mma_k<1>, cudaFuncAttributeMaxDynamicSharedMemorySize, CONV_SMEM);
    cudaFuncSetAttribute(cond1x1s_k, cudaFuncAttributeMaxDynamicSharedMemorySize, COND_SMEM);

    gn_stats_k<<<128, 256>>>(x, mean, rstd);
    gnact_k<<<dim3(64, 4), 256>>>(x, mean, rstd, g1s, g1b, athi, atlo);
    wround_k<<<576, 256>>>(c1w, wh);
    temb_k<<<dim3(16, 4), 256>>>(tt, mw, mb, temb);
    conv_mma_k<0><<<dim3(64, 4), 256, CONV_SMEM>>>(athi, atlo, wh, c1b, temb, nullptr, h1);
    cond1x1s_k<<<dim3(64, 4), 256, COND_SMEM>>>(cond, cw, cbi, khi, kthi, ktlo);
    transpose_k<<<dim3(64, 4), 256>>>(h1, h1T);
    attn_mma_k<<<dim3(32, 4), 256, ATTN_SMEM>>>(h1T, khi, kthi, ktlo, oT);
    transadd_k<<<dim3(64, 4), 256>>>(h1, emb, aim, oT, h2);
    gn_stats_k<<<128, 256>>>(h2, mean, rstd);
    gnact_k<<<dim3(64, 4), 256>>>(h2, mean, rstd, g2s, g2b, athi, atlo);
    wround_k<<<576, 256>>>(c2w, wh);
    conv_mma_k<1><<<dim3(64, 4), 256, CONV_SMEM>>>(athi, atlo, wh, c2b, nullptr, x, out);
}

// round 15
// speedup vs baseline: 3.8072x; 1.2105x over previous
#include <cuda_runtime.h>
#include <cuda_fp16.h>
#include <math.h>
#include <stdint.h>

typedef unsigned long long ull;

#define NB 4
#define NC 128
#define NHW 4096
#define NG 32
#define NTD 512
#define SCALE_Q 0.088388347648318447f  /* 1/sqrt(128) */

// ------------------------- static scratch (no allocations) -------------------------
static __device__ float  g_h1  [NB * NC * NHW];
static __device__ float  g_h2  [NB * NC * NHW];
static __device__ float  g_oT  [NB * NHW * NC];   // attn out [b][w][h][c]
static __device__ float  g_temb[NB * NC];
static __device__ float  g_mean[NB * NG];
static __device__ float  g_rstd[NB * NG];
static __device__ __half g_h1T [NB * NHW * NC];   // [b][w][h][c] * 1/sqrt(C), fp16
static __device__ __half g_khi [NB * NC * NHW];   // K [b][c][u]
static __device__ __half g_kthi[NB * NHW * NC];   // K [b][u][c]
static __device__ __half g_athi[NB * NHW * NC];   // act [b][h][w][c]
static __device__ __half g_wh  [3 * 128 * 384];   // weights [kh][co][kw*128+ci]

// ------------------------- helpers -------------------------
__device__ __forceinline__ void fma2(ull& d, ull a, ull b) {
    asm("fma.rn.f32x2 %0, %1, %2, %0;" : "+l"(d) : "l"(a), "l"(b));
}
__device__ __forceinline__ ull dup2(float x) {
    ull r;
    asm("mov.b64 %0, {%1, %2};" : "=l"(r) : "f"(x), "f"(x));
    return r;
}
__device__ __forceinline__ float2 unp2(ull v) {
    float2 r;
    asm("mov.b64 {%0, %1}, %2;" : "=f"(r.x), "=f"(r.y) : "l"(v));
    return r;
}
__device__ __forceinline__ float siluf(float x) { return x / (1.0f + __expf(-x)); }

__device__ __forceinline__ unsigned packh2(float a, float b) {
    __half2 t = __floats2half2_rn(a, b);
    return *reinterpret_cast<unsigned*>(&t);
}

// fp16 HMMA m16n8k16 (family-safe PTX, f32 accum)
__device__ __forceinline__ void mma_h(float* d, unsigned a0, unsigned a1,
                                      unsigned a2, unsigned a3,
                                      unsigned b0, unsigned b1) {
    asm volatile(
        "mma.sync.aligned.m16n8k16.row.col.f32.f16.f16.f32 "
        "{%0,%1,%2,%3}, {%4,%5,%6,%7}, {%8,%9}, {%0,%1,%2,%3};"
        : "+f"(d[0]), "+f"(d[1]), "+f"(d[2]), "+f"(d[3])
        : "r"(a0), "r"(a1), "r"(a2), "r"(a3), "r"(b0), "r"(b1));
}

// ------------------------- group-norm statistics -------------------------
__global__ void __launch_bounds__(256) gn_stats_k(const float* __restrict__ src,
                                                  float* __restrict__ mean,
                                                  float* __restrict__ rstd) {
    int bg = blockIdx.x;
    const float4* p = (const float4*)(src + bg * 16384);
    float s = 0.f, ss = 0.f;
    for (int i = threadIdx.x; i < 4096; i += 256) {
        float4 v = p[i];
        s  += v.x + v.y + v.z + v.w;
        ss += v.x * v.x + v.y * v.y + v.z * v.z + v.w * v.w;
    }
    for (int off = 16; off; off >>= 1) {
        s  += __shfl_down_sync(0xffffffffu, s,  off);
        ss += __shfl_down_sync(0xffffffffu, ss, off);
    }
    __shared__ float ws[8], wss[8];
    int wid = threadIdx.x >> 5, lane = threadIdx.x & 31;
    if (lane == 0) { ws[wid] = s; wss[wid] = ss; }
    __syncthreads();
    if (threadIdx.x == 0) {
        float ts = 0.f, tss = 0.f;
        for (int i = 0; i < 8; i++) { ts += ws[i]; tss += wss[i]; }
        float m = ts * (1.f / 16384.f);
        float var = tss * (1.f / 16384.f) - m * m;
        mean[bg] = m;
        rstd[bg] = rsqrtf(var + 1e-5f);
    }
}

// ------------- GN + SiLU + transpose + fp16: src[b][c][h][w] -> athi[b][h][w][c] ---
__global__ void __launch_bounds__(256) gnact_k(const float* __restrict__ src,
                                               const float* __restrict__ mean,
                                               const float* __restrict__ rstd,
                                               const float* __restrict__ sc,
                                               const float* __restrict__ bi,
                                               __half* __restrict__ athi) {
    __shared__ float smt[128 * 65];
    __shared__ float a_s[128], b_s[128];
    int h = blockIdx.x, b = blockIdx.y, t = threadIdx.x;
    if (t < 128) {
        float a = rstd[b * 32 + (t >> 2)] * sc[t];
        a_s[t] = a;
        b_s[t] = bi[t] - mean[b * 32 + (t >> 2)] * a;
    }
    __syncthreads();
    for (int i = 0; i < 32; i++) {
        int idx = t + i * 256;
        int c = idx >> 6, w = idx & 63;
        float v = src[(b * 128 + c) * 4096 + h * 64 + w];
        smt[c * 65 + w] = siluf(v * a_s[c] + b_s[c]);
    }
    __syncthreads();
    unsigned* oh = (unsigned*)(athi + (size_t)(b * 64 + h) * 64 * 128);
    for (int i = 0; i < 16; i++) {
        int idx = t + i * 256;                        // 4096 u32
        int w = idx >> 6, cp = idx & 63;
        oh[w * 64 + cp] = packh2(smt[(2 * cp) * 65 + w], smt[(2 * cp + 1) * 65 + w]);
    }
}

// ------------------------- weight reorder + fp16 round -------------------------
__global__ void __launch_bounds__(256) wround_k(const float* __restrict__ wgt,
                                                __half* __restrict__ wh) {
    int o = blockIdx.x * 256 + threadIdx.x;          // 147456 outputs
    int kh = o / 49152, r = o % 49152;
    int co = r / 384,  r2 = r % 384;
    int kw = r2 >> 7,  ci = r2 & 127;
    wh[o] = __float2half_rn(wgt[((co * 128 + ci) * 3 + kh) * 3 + kw]);
}

// ------------------------- time embedding: warp per co -------------------------
__global__ void __launch_bounds__(256) temb_k(const float* __restrict__ t,
                                              const float* __restrict__ mw,
                                              const float* __restrict__ mb,
                                              float* __restrict__ temb) {
    __shared__ float st[NTD];
    int b = blockIdx.y, tid = threadIdx.x;
    int lane = tid & 31, wid = tid >> 5;
    for (int k = tid; k < NTD; k += 256) st[k] = siluf(t[b * NTD + k]);
    __syncthreads();
    int co = blockIdx.x * 8 + wid;
    const float* wr = mw + co * NTD;
    float acc = 0.f;
#pragma unroll
    for (int j = 0; j < 16; j++) {
        int k = lane + 32 * j;
        acc += st[k] * wr[k];
    }
    for (int off = 16; off; off >>= 1)
        acc += __shfl_down_sync(0xffffffffu, acc, off);
    if (lane == 0) temb[b * NC + co] = acc + mb[co];
}

// ------------------------- tensor-core 3x3 conv (single fp16) -------------------------
#define CV_WH 0
#define CV_XH (128 * 68)
#define CONV_SMEM ((128 * 68 + 64 * 68) * 4)

template <int MODE>
__global__ void __launch_bounds__(256, 2) conv_mma_k(
        const __half* __restrict__ athi, const __half* __restrict__ wh,
        const float* __restrict__ bias, const float* __restrict__ temb,
        const float* __restrict__ resid, float* __restrict__ dst) {
    extern __shared__ __align__(16) unsigned smc[];
    unsigned* Wh = smc + CV_WH;
    unsigned* Xh = smc + CV_XH;
    int t = threadIdx.x, lane = t & 31, wid = t >> 5;
    int h = blockIdx.x, b = blockIdx.y;
    int g = lane >> 2, tq = lane & 3;
    int mrow = wid * 16;

    float o[8][4];
#pragma unroll
    for (int n = 0; n < 8; n++)
#pragma unroll
        for (int k = 0; k < 4; k++) o[n][k] = 0.f;

    for (int tap = 0; tap < 9; tap++) {
        int kh = tap / 3, kw = tap % 3;
        int hh = h + kh - 1;
        if (hh < 0 || hh > 63) continue;
        __syncthreads();
#pragma unroll
        for (int i = 0; i < 4; i++) {
            int idx = t + i * 256;
            int w = idx >> 4, q = idx & 15;
            int ws = w + kw - 1;
            uint4 vh = make_uint4(0, 0, 0, 0);
            if (ws >= 0 && ws < 64)
                vh = ((const uint4*)athi)[(size_t)((b * 64 + hh) * 64 + ws) * 16 + q];
            *(uint4*)(Xh + w * 68 + q * 4) = vh;
        }
#pragma unroll
        for (int i = 0; i < 8; i++) {
            int idx = t + i * 256;
            int co = idx >> 4, q = idx & 15;
            *(uint4*)(Wh + co * 68 + q * 4) =
                ((const uint4*)wh)[(size_t)(kh * 128 + co) * 48 + kw * 16 + q];
        }
        __syncthreads();
#pragma unroll
        for (int ks = 0; ks < 8; ks++) {
            int r0 = (mrow + g) * 68 + 8 * ks + tq, r1 = r0 + 8 * 68;
            unsigned a0 = Wh[r0], a1 = Wh[r1], a2 = Wh[r0 + 4], a3 = Wh[r1 + 4];
#pragma unroll
            for (int n = 0; n < 8; n++) {
                int bi = (8 * n + g) * 68 + 8 * ks + tq;
                mma_h(o[n], a0, a1, a2, a3, Xh[bi], Xh[bi + 4]);
            }
        }
    }
    int co0 = mrow + g;
    float add0 = bias[co0]     + (MODE == 0 ? temb[b * 128 + co0]     : 0.f);
    float add1 = bias[co0 + 8] + (MODE == 0 ? temb[b * 128 + co0 + 8] : 0.f);
#pragma unroll
    for (int n = 0; n < 8; n++) {
        int w = 8 * n + 2 * tq;
        size_t i0 = ((size_t)(b * 128 + co0) * 64 + h) * 64 + w;
        size_t i1 = i0 + 8 * 4096;
        float v00 = o[n][0] + add0, v01 = o[n][1] + add0;
        float v10 = o[n][2] + add1, v11 = o[n][3] + add1;
        if (MODE == 1) {
            v00 += resid[i0]; v01 += resid[i0 + 1];
            v10 += resid[i1]; v11 += resid[i1 + 1];
        }
        *(float2*)(dst + i0) = make_float2(v00, v01);
        *(float2*)(dst + i1) = make_float2(v10, v11);
    }
}

// --------------- cond 1x1 projection + fp16 round, both orientations ---------------
#define COND_SMEM ((128 * 64 + 128 * 65) * 4)
__global__ void __launch_bounds__(256) cond1x1s_k(const float* __restrict__ cond,
                                                  const float* __restrict__ wt,
                                                  const float* __restrict__ bias,
                                                  __half* __restrict__ khi,
                                                  __half* __restrict__ kthi) {
    extern __shared__ __align__(16) float smf[];
    float* ct = smf;                 // [128ci][64u]
    float* ss = smf + 128 * 64;      // [128co][65]
    int u0 = blockIdx.x * 64, b = blockIdx.y, t = threadIdx.x;
    for (int i = 0; i < 32; i++) {
        int idx = t + i * 256;
        ct[idx] = cond[(b * 128 + (idx >> 6)) * 4096 + u0 + (idx & 63)];
    }
    __syncthreads();
    {
        int co = t & 127, uh = t >> 7;
        ull acc[16];
#pragma unroll
        for (int j = 0; j < 16; j++) acc[j] = 0ull;
        const float* wrow = wt + co * 128;
        for (int ci = 0; ci < 128; ci++) {
            ull wv = dup2(__ldg(wrow + ci));
            const ull* kr = (const ull*)&ct[ci * 64 + uh * 32];
#pragma unroll
            for (int j = 0; j < 16; j++) fma2(acc[j], wv, kr[j]);
        }
        float bv = bias[co];
        float* op = ss + co * 65 + uh * 32;
#pragma unroll
        for (int j = 0; j < 16; j++) {
            float2 v = unp2(acc[j]);
            op[2 * j]     = v.x + bv;
            op[2 * j + 1] = v.y + bv;
        }
    }
    __syncthreads();
    {   // [c][u] orientation
        int c = t >> 1, uh = (t & 1) * 32;
        unsigned hi[16];
#pragma unroll
        for (int j = 0; j < 16; j++)
            hi[j] = packh2(ss[c * 65 + uh + 2 * j], ss[c * 65 + uh + 2 * j + 1]);
        uint4* dh = (uint4*)((unsigned*)khi + (size_t)(b * 128 + c) * 2048 + (u0 + uh) / 2);
#pragma unroll
        for (int q = 0; q < 4; q++)
            dh[q] = make_uint4(hi[4*q], hi[4*q+1], hi[4*q+2], hi[4*q+3]);
    }
    {   // [u][c] orientation
        int u = t & 63, ch = (t >> 6) * 32;
        unsigned hi[16];
#pragma unroll
        for (int j = 0; j < 16; j++)
            hi[j] = packh2(ss[(ch + 2 * j) * 65 + u], ss[(ch + 2 * j + 1) * 65 + u]);
        uint4* dh = (uint4*)((unsigned*)kthi + (size_t)(b * 4096 + u0 + u) * 64 + ch / 2);
#pragma unroll
        for (int q = 0; q < 4; q++)
            dh[q] = make_uint4(hi[4*q], hi[4*q+1], hi[4*q+2], hi[4*q+3]);
    }
}

// ------------------ transpose + scale + fp16 round: h1 -> h1T[b][w][h][c] ------------------
__global__ void __launch_bounds__(256) transpose_k(const float* __restrict__ h1,
                                                   __half* __restrict__ h1T) {
    __shared__ float sm[128 * 65];
    int h = blockIdx.x, b = blockIdx.y, t = threadIdx.x;
    const float* src = h1 + ((b * 128) * 64 + h) * 64;
    for (int i = 0; i < 32; i++) {
        int idx = t + i * 256;
        int c = idx >> 6, w = idx & 63;
        sm[c * 65 + w] = src[c * 4096 + w] * SCALE_Q;
    }
    __syncthreads();
    unsigned* dst = (unsigned*)h1T;
    for (int i = 0; i < 16; i++) {
        int idx = t + i * 256;
        int w = idx >> 6, cp = idx & 63;
        dst[(size_t)((b * 64 + w) * 64 + h) * 64 + cp] =
            packh2(sm[(2 * cp) * 65 + w], sm[(2 * cp + 1) * 65 + w]);
    }
}

// ------------- transadd: h2 = h1 + contrast_embed[aim[b]][c] + oT^T -------------
__global__ void __launch_bounds__(256) transadd_k(const float* __restrict__ h1,
                                                  const float* __restrict__ emb,
                                                  const int* __restrict__ aim,
                                                  const float* __restrict__ oT,
                                                  float* __restrict__ h2) {
    __shared__ float sm[64 * 129];
    int h = blockIdx.x, b = blockIdx.y, t = threadIdx.x;
    int ai = aim[b];
    for (int i = 0; i < 32; i++) {
        int idx = t + i * 256;
        int w = idx >> 7, c = idx & 127;
        sm[w * 129 + c] = oT[((b * 64 + w) * 64 + h) * 128 + c];
    }
    __syncthreads();
    for (int i = 0; i < 32; i++) {
        int idx = t + i * 256;
        int c = idx >> 6, w = idx & 63;
        size_t gi = (size_t)(b * 128 + c) * 4096 + h * 64 + w;
        h2[gi] = h1[gi] + emb[ai * 128 + c] + sm[w * 129 + c];
    }
}

// ------------------------- mma.sync attention (single fp16 all GEMMs) ---------------
#define OFF_AH   0                       /* [128m][68] */
#define OFF_KTH  (OFF_AH + 128 * 68)     /* [64u][68]  */
#define OFF_KCH  (OFF_KTH + 64 * 68)     /* [128c][36] */
#define OFF_SST  (OFF_KCH + 128 * 36)    /* f32 [64u][129] */
#define OFF_PH   (OFF_SST + 64 * 129)    /* [128m][36] */
#define OFF_REDS (OFF_PH + 128 * 36)
#define OFF_RSM  (OFF_REDS + 256)
#define ATTN_SMEM ((OFF_RSM + 128) * 4)

__global__ void __launch_bounds__(256, 1) attn_mma_k(const __half* __restrict__ h1T,
        const __half* __restrict__ khi, const __half* __restrict__ kthi,
        float* __restrict__ oT) {
    extern __shared__ __align__(16) unsigned sma[];
    unsigned* Ah   = sma + OFF_AH;
    unsigned* KTh  = sma + OFF_KTH;
    unsigned* Kch  = sma + OFF_KCH;
    float*    SsT  = (float*)(sma + OFF_SST);
    unsigned* Ph   = sma + OFF_PH;
    float*    reds = (float*)(sma + OFF_REDS);
    float*    rsm  = (float*)(sma + OFF_RSM);

    int t = threadIdx.x, lane = t & 31, wid = t >> 5;
    int wp = blockIdx.x, b = blockIdx.y;
    int g = lane >> 2, tq = lane & 3;
    int mrow = wid * 16;

#pragma unroll
    for (int i = 0; i < 8; i++) {
        int idx = t + i * 256;
        int m = idx >> 4, q = idx & 15;
        *(uint4*)(Ah + m * 68 + q * 4) =
            ((const uint4*)h1T)[(size_t)((b * 64 + 2 * wp + (m >> 6)) * 64 + (m & 63)) * 16 + q];
    }

    float o[16][4];
#pragma unroll
    for (int n = 0; n < 16; n++)
#pragma unroll
        for (int k = 0; k < 4; k++) o[n][k] = 0.f;

    for (int tile = 0; tile < 64; tile++) {
        int u0 = tile * 64;
        __syncthreads();
#pragma unroll
        for (int i = 0; i < 4; i++) {
            int idx = t + i * 256;
            {
                int u = idx >> 4, q = idx & 15;
                *(uint4*)(KTh + u * 68 + q * 4) =
                    ((const uint4*)kthi)[(size_t)(b * 4096 + u0 + u) * 16 + q];
            }
            {
                int c = idx >> 3, q = idx & 7;
                *(uint4*)(Kch + c * 36 + q * 4) =
                    ((const uint4*)khi)[(size_t)(b * 128 + c) * 512 + tile * 8 + q];
            }
        }
        __syncthreads();

        // GEMM1: S = Ah * KTh
        float s[8][4];
#pragma unroll
        for (int n = 0; n < 8; n++)
#pragma unroll
            for (int k = 0; k < 4; k++) s[n][k] = 0.f;
#pragma unroll
        for (int ks = 0; ks < 8; ks++) {
            int r0 = (mrow + g) * 68 + 8 * ks + tq;
            int r1 = r0 + 8 * 68;
            unsigned a0 = Ah[r0], a1 = Ah[r1], a2 = Ah[r0 + 4], a3 = Ah[r1 + 4];
#pragma unroll
            for (int n = 0; n < 8; n++) {
                int bi = (8 * n + g) * 68 + 8 * ks + tq;
                mma_h(s[n], a0, a1, a2, a3, KTh[bi], KTh[bi + 4]);
            }
        }
#pragma unroll
        for (int n = 0; n < 8; n++) {
            int ub = 8 * n + 2 * tq;
            SsT[ub * 129 + mrow + g]           = s[n][0];
            SsT[(ub + 1) * 129 + mrow + g]     = s[n][1];
            SsT[ub * 129 + mrow + g + 8]       = s[n][2];
            SsT[(ub + 1) * 129 + mrow + g + 8] = s[n][3];
        }
        __syncthreads();

        // exp (no max-sub) + per-w-half column sums
        {
            int u = t & 63, qq = t >> 6;
            float* col = SsT + u * 129 + qq * 32;
            float ps = 0.f;
#pragma unroll
            for (int j = 0; j < 32; j++) {
                float e = __expf(col[j]);
                col[j] = e;
                ps += e;
            }
            reds[qq * 64 + u] = ps;
        }
        __syncthreads();
        if (t < 128) {
            int half = t >> 6, u = t & 63;
            rsm[half * 64 + u] = 1.f / (reds[2 * half * 64 + u] + reds[(2 * half + 1) * 64 + u]);
        }
        __syncthreads();

        // P = E * rs -> fp16 round
        {
            int m = t >> 1, uh = (t & 1) * 32, half = m >> 6;
            const float* rp = rsm + half * 64;
            unsigned* ph = Ph + m * 36 + (uh >> 1);
#pragma unroll
            for (int j = 0; j < 16; j++) {
                int u = uh + 2 * j;
                ph[j] = packh2(SsT[u * 129 + m] * rp[u],
                               SsT[(u + 1) * 129 + m] * rp[u + 1]);
            }
        }
        __syncthreads();

        // GEMM2: O += Ph * Kch
#pragma unroll
        for (int ks = 0; ks < 4; ks++) {
            int r0 = (mrow + g) * 36 + 8 * ks + tq;
            int r1 = r0 + 8 * 36;
            unsigned p0 = Ph[r0], p1 = Ph[r1], p2 = Ph[r0 + 4], p3 = Ph[r1 + 4];
#pragma unroll
            for (int n = 0; n < 16; n++) {
                int bi = (8 * n + g) * 36 + 8 * ks + tq;
                mma_h(o[n], p0, p1, p2, p3, Kch[bi], Kch[bi + 4]);
            }
        }
    }

    {
        size_t base = (size_t)(b * 64 + 2 * wp + (mrow >> 6)) * 64;
        int hrow = (mrow & 63) + g;
        float* r0 = oT + (base + hrow) * 128;
        float* r1 = oT + (base + hrow + 8) * 128;
#pragma unroll
        for (int n = 0; n < 16; n++) {
            *(float2*)(r0 + 8 * n + 2 * tq) = make_float2(o[n][0], o[n][1]);
            *(float2*)(r1 + 8 * n + 2 * tq) = make_float2(o[n][2], o[n][3]);
        }
    }
}

// ------------------------- launch -------------------------
extern "C" void kernel_launch(void* const* d_in, const int* in_sizes, int n_in,
                              void* d_out, int out_size) {
    const float* x    = (const float*)d_in[0];
    const float* tt   = (const float*)d_in[1];
    const int*   aim  = (const int*)d_in[2];
    const float* cond = (const float*)d_in[3];
    const float* g1s  = (const float*)d_in[4];
    const float* g1b  = (const float*)d_in[5];
    const float* c1w  = (const float*)d_in[6];
    const float* c1b  = (const float*)d_in[7];
    const float* mw   = (const float*)d_in[8];
    const float* mb   = (const float*)d_in[9];
    const float* cw   = (const float*)d_in[10];
    const float* cbi  = (const float*)d_in[11];
    const float* g2s  = (const float*)d_in[12];
    const float* g2b  = (const float*)d_in[13];
    const float* c2w  = (const float*)d_in[14];
    const float* c2b  = (const float*)d_in[15];
    const float* emb  = (const float*)d_in[16];
    float* out = (float*)d_out;

    float *h1, *h2, *oT, *temb, *mean, *rstd;
    __half *h1T, *khi, *kthi, *athi, *wh;
    cudaGetSymbolAddress((void**)&h1,   g_h1);
    cudaGetSymbolAddress((void**)&h2,   g_h2);
    cudaGetSymbolAddress((void**)&oT,   g_oT);
    cudaGetSymbolAddress((void**)&temb, g_temb);
    cudaGetSymbolAddress((void**)&mean, g_mean);
    cudaGetSymbolAddress((void**)&rstd, g_rstd);
    cudaGetSymbolAddress((void**)&h1T,  g_h1T);
    cudaGetSymbolAddress((void**)&khi,  g_khi);
    cudaGetSymbolAddress((void**)&kthi, g_kthi);
    cudaGetSymbolAddress((void**)&athi, g_athi);
    cudaGetSymbolAddress((void**)&wh,   g_wh);

    cudaFuncSetAttribute(attn_mma_k, cudaFuncAttributeMaxDynamicSharedMemorySize, ATTN_SMEM);
    cudaFuncSetAttribute(conv_mma_k<0>, cudaFuncAttributeMaxDynamicSharedMemorySize, CONV_SMEM);
    cudaFuncSetAttribute(conv_mma_k<1>, cudaFuncAttributeMaxDynamicSharedMemorySize, CONV_SMEM);
    cudaFuncSetAttribute(cond1x1s_k, cudaFuncAttributeMaxDynamicSharedMemorySize, COND_SMEM);

    gn_stats_k<<<128, 256>>>(x, mean, rstd);
    gnact_k<<<dim3(64, 4), 256>>>(x, mean, rstd, g1s, g1b, athi);
    wround_k<<<576, 256>>>(c1w, wh);
    temb_k<<<dim3(16, 4), 256>>>(tt, mw, mb, temb);
    conv_mma_k<0><<<dim3(64, 4), 256, CONV_SMEM>>>(athi, wh, c1b, temb, nullptr, h1);
    cond1x1s_k<<<dim3(64, 4), 256, COND_SMEM>>>(cond, cw, cbi, khi, kthi);
    transpose_k<<<dim3(64, 4), 256>>>(h1, h1T);
    attn_mma_k<<<dim3(32, 4), 256, ATTN_SMEM>>>(h1T, khi, kthi, oT);
    transadd_k<<<dim3(64, 4), 256>>>(h1, emb, aim, oT, h2);
    gn_stats_k<<<128, 256>>>(h2, mean, rstd);
    gnact_k<<<dim3(64, 4), 256>>>(h2, mean, rstd, g2s, g2b, athi);
    wround_k<<<576, 256>>>(c2w, wh);
    conv_mma_k<1><<<dim3(64, 4), 256, CONV_SMEM>>>(athi, wh, c2b, nullptr, x, out);
}

// round 17
// speedup vs baseline: 4.2059x; 1.1047x over previous
#include <cuda_runtime.h>
#include <cuda_fp16.h>
#include <math.h>
#include <stdint.h>

typedef unsigned long long ull;

#define NB 4
#define NC 128
#define NHW 4096
#define NG 32
#define NTD 512
#define SCALE_Q 0.088388347648318447f  /* 1/sqrt(128) */

// ------------------------- static scratch (no allocations) -------------------------
static __device__ float  g_h1  [NB * NC * NHW];
static __device__ float  g_h2  [NB * NC * NHW];
static __device__ float  g_oT  [NB * NHW * NC];   // attn out [b][w][h][c]
static __device__ float  g_temb[NB * NC];
static __device__ float  g_mean[NB * NG];
static __device__ float  g_rstd[NB * NG];
static __device__ __half g_h1T [NB * NHW * NC];   // [b][w][h][c] * 1/sqrt(C), fp16
static __device__ __half g_khi [NB * NC * NHW];   // K [b][c][u]
static __device__ __half g_kthi[NB * NHW * NC];   // K [b][u][c]
static __device__ __half g_athi[NB * NHW * NC];   // act [b][h][w][c]
static __device__ __half g_wh  [3 * 128 * 384];   // weights [kh][co][kw*128+ci]

// ------------------------- helpers -------------------------
__device__ __forceinline__ void fma2(ull& d, ull a, ull b) {
    asm("fma.rn.f32x2 %0, %1, %2, %0;" : "+l"(d) : "l"(a), "l"(b));
}
__device__ __forceinline__ ull dup2(float x) {
    ull r;
    asm("mov.b64 %0, {%1, %2};" : "=l"(r) : "f"(x), "f"(x));
    return r;
}
__device__ __forceinline__ float2 unp2(ull v) {
    float2 r;
    asm("mov.b64 {%0, %1}, %2;" : "=f"(r.x), "=f"(r.y) : "l"(v));
    return r;
}
__device__ __forceinline__ float siluf(float x) { return x / (1.0f + __expf(-x)); }

__device__ __forceinline__ unsigned packh2(float a, float b) {
    __half2 t = __floats2half2_rn(a, b);
    return *reinterpret_cast<unsigned*>(&t);
}

// fp16 HMMA m16n8k16 (family-safe PTX, f32 accum)
__device__ __forceinline__ void mma_h(float* d, unsigned a0, unsigned a1,
                                      unsigned a2, unsigned a3,
                                      unsigned b0, unsigned b1) {
    asm volatile(
        "mma.sync.aligned.m16n8k16.row.col.f32.f16.f16.f32 "
        "{%0,%1,%2,%3}, {%4,%5,%6,%7}, {%8,%9}, {%0,%1,%2,%3};"
        : "+f"(d[0]), "+f"(d[1]), "+f"(d[2]), "+f"(d[3])
        : "r"(a0), "r"(a1), "r"(a2), "r"(a3), "r"(b0), "r"(b1));
}

// ------------------------- group-norm statistics -------------------------
__global__ void __launch_bounds__(256) gn_stats_k(const float* __restrict__ src,
                                                  float* __restrict__ mean,
                                                  float* __restrict__ rstd) {
    int bg = blockIdx.x;
    const float4* p = (const float4*)(src + bg * 16384);
    float s = 0.f, ss = 0.f;
    for (int i = threadIdx.x; i < 4096; i += 256) {
        float4 v = p[i];
        s  += v.x + v.y + v.z + v.w;
        ss += v.x * v.x + v.y * v.y + v.z * v.z + v.w * v.w;
    }
    for (int off = 16; off; off >>= 1) {
        s  += __shfl_down_sync(0xffffffffu, s,  off);
        ss += __shfl_down_sync(0xffffffffu, ss, off);
    }
    __shared__ float ws[8], wss[8];
    int wid = threadIdx.x >> 5, lane = threadIdx.x & 31;
    if (lane == 0) { ws[wid] = s; wss[wid] = ss; }
    __syncthreads();
    if (threadIdx.x == 0) {
        float ts = 0.f, tss = 0.f;
        for (int i = 0; i < 8; i++) { ts += ws[i]; tss += wss[i]; }
        float m = ts * (1.f / 16384.f);
        float var = tss * (1.f / 16384.f) - m * m;
        mean[bg] = m;
        rstd[bg] = rsqrtf(var + 1e-5f);
    }
}

// ------------- GN + SiLU + transpose + fp16: src[b][c][h][w] -> athi[b][h][w][c] ---
__global__ void __launch_bounds__(256) gnact_k(const float* __restrict__ src,
                                               const float* __restrict__ mean,
                                               const float* __restrict__ rstd,
                                               const float* __restrict__ sc,
                                               const float* __restrict__ bi,
                                               __half* __restrict__ athi) {
    __shared__ float smt[128 * 65];
    __shared__ float a_s[128], b_s[128];
    int h = blockIdx.x, b = blockIdx.y, t = threadIdx.x;
    if (t < 128) {
        float a = rstd[b * 32 + (t >> 2)] * sc[t];
        a_s[t] = a;
        b_s[t] = bi[t] - mean[b * 32 + (t >> 2)] * a;
    }
    __syncthreads();
    for (int i = 0; i < 32; i++) {
        int idx = t + i * 256;
        int c = idx >> 6, w = idx & 63;
        float v = src[(b * 128 + c) * 4096 + h * 64 + w];
        smt[c * 65 + w] = siluf(v * a_s[c] + b_s[c]);
    }
    __syncthreads();
    unsigned* oh = (unsigned*)(athi + (size_t)(b * 64 + h) * 64 * 128);
    for (int i = 0; i < 16; i++) {
        int idx = t + i * 256;                        // 4096 u32
        int w = idx >> 6, cp = idx & 63;
        oh[w * 64 + cp] = packh2(smt[(2 * cp) * 65 + w], smt[(2 * cp + 1) * 65 + w]);
    }
}

// ------------------------- weight reorder + fp16 round -------------------------
__global__ void __launch_bounds__(256) wround_k(const float* __restrict__ wgt,
                                                __half* __restrict__ wh) {
    int o = blockIdx.x * 256 + threadIdx.x;          // 147456 outputs
    int kh = o / 49152, r = o % 49152;
    int co = r / 384,  r2 = r % 384;
    int kw = r2 >> 7,  ci = r2 & 127;
    wh[o] = __float2half_rn(wgt[((co * 128 + ci) * 3 + kh) * 3 + kw]);
}

// ------------------------- time embedding: warp per co -------------------------
__global__ void __launch_bounds__(256) temb_k(const float* __restrict__ t,
                                              const float* __restrict__ mw,
                                              const float* __restrict__ mb,
                                              float* __restrict__ temb) {
    __shared__ float st[NTD];
    int b = blockIdx.y, tid = threadIdx.x;
    int lane = tid & 31, wid = tid >> 5;
    for (int k = tid; k < NTD; k += 256) st[k] = siluf(t[b * NTD + k]);
    __syncthreads();
    int co = blockIdx.x * 8 + wid;
    const float* wr = mw + co * NTD;
    float acc = 0.f;
#pragma unroll
    for (int j = 0; j < 16; j++) {
        int k = lane + 32 * j;
        acc += st[k] * wr[k];
    }
    for (int off = 16; off; off >>= 1)
        acc += __shfl_down_sync(0xffffffffu, acc, off);
    if (lane == 0) temb[b * NC + co] = acc + mb[co];
}

// ------------------------- tensor-core 3x3 conv (single fp16) -------------------------
#define CV_WH 0
#define CV_XH (128 * 68)
#define CONV_SMEM ((128 * 68 + 64 * 68) * 4)

template <int MODE>
__global__ void __launch_bounds__(256, 2) conv_mma_k(
        const __half* __restrict__ athi, const __half* __restrict__ wh,
        const float* __restrict__ bias, const float* __restrict__ temb,
        const float* __restrict__ resid, float* __restrict__ dst) {
    extern __shared__ __align__(16) unsigned smc[];
    unsigned* Wh = smc + CV_WH;
    unsigned* Xh = smc + CV_XH;
    int t = threadIdx.x, lane = t & 31, wid = t >> 5;
    int h = blockIdx.x, b = blockIdx.y;
    int g = lane >> 2, tq = lane & 3;
    int mrow = wid * 16;

    float o[8][4];
#pragma unroll
    for (int n = 0; n < 8; n++)
#pragma unroll
        for (int k = 0; k < 4; k++) o[n][k] = 0.f;

    for (int tap = 0; tap < 9; tap++) {
        int kh = tap / 3, kw = tap % 3;
        int hh = h + kh - 1;
        if (hh < 0 || hh > 63) continue;
        __syncthreads();
#pragma unroll
        for (int i = 0; i < 4; i++) {
            int idx = t + i * 256;
            int w = idx >> 4, q = idx & 15;
            int ws = w + kw - 1;
            uint4 vh = make_uint4(0, 0, 0, 0);
            if (ws >= 0 && ws < 64)
                vh = ((const uint4*)athi)[(size_t)((b * 64 + hh) * 64 + ws) * 16 + q];
            *(uint4*)(Xh + w * 68 + q * 4) = vh;
        }
#pragma unroll
        for (int i = 0; i < 8; i++) {
            int idx = t + i * 256;
            int co = idx >> 4, q = idx & 15;
            *(uint4*)(Wh + co * 68 + q * 4) =
                ((const uint4*)wh)[(size_t)(kh * 128 + co) * 48 + kw * 16 + q];
        }
        __syncthreads();
#pragma unroll
        for (int ks = 0; ks < 8; ks++) {
            int r0 = (mrow + g) * 68 + 8 * ks + tq, r1 = r0 + 8 * 68;
            unsigned a0 = Wh[r0], a1 = Wh[r1], a2 = Wh[r0 + 4], a3 = Wh[r1 + 4];
#pragma unroll
            for (int n = 0; n < 8; n++) {
                int bi = (8 * n + g) * 68 + 8 * ks + tq;
                mma_h(o[n], a0, a1, a2, a3, Xh[bi], Xh[bi + 4]);
            }
        }
    }
    int co0 = mrow + g;
    float add0 = bias[co0]     + (MODE == 0 ? temb[b * 128 + co0]     : 0.f);
    float add1 = bias[co0 + 8] + (MODE == 0 ? temb[b * 128 + co0 + 8] : 0.f);
#pragma unroll
    for (int n = 0; n < 8; n++) {
        int w = 8 * n + 2 * tq;
        size_t i0 = ((size_t)(b * 128 + co0) * 64 + h) * 64 + w;
        size_t i1 = i0 + 8 * 4096;
        float v00 = o[n][0] + add0, v01 = o[n][1] + add0;
        float v10 = o[n][2] + add1, v11 = o[n][3] + add1;
        if (MODE == 1) {
            v00 += resid[i0]; v01 += resid[i0 + 1];
            v10 += resid[i1]; v11 += resid[i1 + 1];
        }
        *(float2*)(dst + i0) = make_float2(v00, v01);
        *(float2*)(dst + i1) = make_float2(v10, v11);
    }
}

// --------------- cond 1x1 projection + fp16 round, both orientations ---------------
#define COND_SMEM ((128 * 64 + 128 * 65) * 4)
__global__ void __launch_bounds__(256) cond1x1s_k(const float* __restrict__ cond,
                                                  const float* __restrict__ wt,
                                                  const float* __restrict__ bias,
                                                  __half* __restrict__ khi,
                                                  __half* __restrict__ kthi) {
    extern __shared__ __align__(16) float smf[];
    float* ct = smf;                 // [128ci][64u]
    float* ss = smf + 128 * 64;      // [128co][65]
    int u0 = blockIdx.x * 64, b = blockIdx.y, t = threadIdx.x;
    for (int i = 0; i < 32; i++) {
        int idx = t + i * 256;
        ct[idx] = cond[(b * 128 + (idx >> 6)) * 4096 + u0 + (idx & 63)];
    }
    __syncthreads();
    {
        int co = t & 127, uh = t >> 7;
        ull acc[16];
#pragma unroll
        for (int j = 0; j < 16; j++) acc[j] = 0ull;
        const float* wrow = wt + co * 128;
        for (int ci = 0; ci < 128; ci++) {
            ull wv = dup2(__ldg(wrow + ci));
            const ull* kr = (const ull*)&ct[ci * 64 + uh * 32];
#pragma unroll
            for (int j = 0; j < 16; j++) fma2(acc[j], wv, kr[j]);
        }
        float bv = bias[co];
        float* op = ss + co * 65 + uh * 32;
#pragma unroll
        for (int j = 0; j < 16; j++) {
            float2 v = unp2(acc[j]);
            op[2 * j]     = v.x + bv;
            op[2 * j + 1] = v.y + bv;
        }
    }
    __syncthreads();
    {   // [c][u] orientation
        int c = t >> 1, uh = (t & 1) * 32;
        unsigned hi[16];
#pragma unroll
        for (int j = 0; j < 16; j++)
            hi[j] = packh2(ss[c * 65 + uh + 2 * j], ss[c * 65 + uh + 2 * j + 1]);
        uint4* dh = (uint4*)((unsigned*)khi + (size_t)(b * 128 + c) * 2048 + (u0 + uh) / 2);
#pragma unroll
        for (int q = 0; q < 4; q++)
            dh[q] = make_uint4(hi[4*q], hi[4*q+1], hi[4*q+2], hi[4*q+3]);
    }
    {   // [u][c] orientation
        int u = t & 63, ch = (t >> 6) * 32;
        unsigned hi[16];
#pragma unroll
        for (int j = 0; j < 16; j++)
            hi[j] = packh2(ss[(ch + 2 * j) * 65 + u], ss[(ch + 2 * j + 1) * 65 + u]);
        uint4* dh = (uint4*)((unsigned*)kthi + (size_t)(b * 4096 + u0 + u) * 64 + ch / 2);
#pragma unroll
        for (int q = 0; q < 4; q++)
            dh[q] = make_uint4(hi[4*q], hi[4*q+1], hi[4*q+2], hi[4*q+3]);
    }
}

// ------------------ transpose + scale + fp16 round: h1 -> h1T[b][w][h][c] ------------------
__global__ void __launch_bounds__(256) transpose_k(const float* __restrict__ h1,
                                                   __half* __restrict__ h1T) {
    __shared__ float sm[128 * 65];
    int h = blockIdx.x, b = blockIdx.y, t = threadIdx.x;
    const float* src = h1 + ((b * 128) * 64 + h) * 64;
    for (int i = 0; i < 32; i++) {
        int idx = t + i * 256;
        int c = idx >> 6, w = idx & 63;
        sm[c * 65 + w] = src[c * 4096 + w] * SCALE_Q;
    }
    __syncthreads();
    unsigned* dst = (unsigned*)h1T;
    for (int i = 0; i < 16; i++) {
        int idx = t + i * 256;
        int w = idx >> 6, cp = idx & 63;
        dst[(size_t)((b * 64 + w) * 64 + h) * 64 + cp] =
            packh2(sm[(2 * cp) * 65 + w], sm[(2 * cp + 1) * 65 + w]);
    }
}

// ------------- transadd: h2 = h1 + contrast_embed[aim[b]][c] + oT^T -------------
__global__ void __launch_bounds__(256) transadd_k(const float* __restrict__ h1,
                                                  const float* __restrict__ emb,
                                                  const int* __restrict__ aim,
                                                  const float* __restrict__ oT,
                                                  float* __restrict__ h2) {
    __shared__ float sm[64 * 129];
    int h = blockIdx.x, b = blockIdx.y, t = threadIdx.x;
    int ai = aim[b];
    for (int i = 0; i < 32; i++) {
        int idx = t + i * 256;
        int w = idx >> 7, c = idx & 127;
        sm[w * 129 + c] = oT[((b * 64 + w) * 64 + h) * 128 + c];
    }
    __syncthreads();
    for (int i = 0; i < 32; i++) {
        int idx = t + i * 256;
        int c = idx >> 6, w = idx & 63;
        size_t gi = (size_t)(b * 128 + c) * 4096 + h * 64 + w;
        h2[gi] = h1[gi] + emb[ai * 128 + c] + sm[w * 129 + c];
    }
}

// ------------------------- mma.sync attention (fused exp, shfl sums, K prefetch) ---------
#define OFF_AH   0                       /* [128m][68] */
#define OFF_KTH  (OFF_AH + 128 * 68)     /* [64u][68]  */
#define OFF_KCH  (OFF_KTH + 64 * 68)     /* [128c][36] */
#define OFF_SST  (OFF_KCH + 128 * 36)    /* f32 [64u][132] */
#define OFF_PH   (OFF_SST + 64 * 132)    /* [128m][36] */
#define OFF_RSM  (OFF_PH + 128 * 36)     /* f32 [2][64] */
#define ATTN_SMEM ((OFF_RSM + 128) * 4)

__global__ void __launch_bounds__(256, 1) attn_mma_k(const __half* __restrict__ h1T,
        const __half* __restrict__ khi, const __half* __restrict__ kthi,
        float* __restrict__ oT) {
    extern __shared__ __align__(16) unsigned sma[];
    unsigned* Ah   = sma + OFF_AH;
    unsigned* KTh  = sma + OFF_KTH;
    unsigned* Kch  = sma + OFF_KCH;
    float*    SsT  = (float*)(sma + OFF_SST);
    unsigned* Ph   = sma + OFF_PH;
    float*    rsm  = (float*)(sma + OFF_RSM);

    int t = threadIdx.x, lane = t & 31, wid = t >> 5;
    int wp = blockIdx.x, b = blockIdx.y;
    int g = lane >> 2, tq = lane & 3;
    int mrow = wid * 16;

    // A tile (128 rows = 2w x 64h), fp16 raw copy
#pragma unroll
    for (int i = 0; i < 8; i++) {
        int idx = t + i * 256;
        int m = idx >> 4, q = idx & 15;
        *(uint4*)(Ah + m * 68 + q * 4) =
            ((const uint4*)h1T)[(size_t)((b * 64 + 2 * wp + (m >> 6)) * 64 + (m & 63)) * 16 + q];
    }

    float o[16][4];
#pragma unroll
    for (int n = 0; n < 16; n++)
#pragma unroll
        for (int k = 0; k < 4; k++) o[n][k] = 0.f;

    // ---- K-tile register prefetch (tile 0) ----
    uint4 krt[4], krc[4];
#pragma unroll
    for (int i = 0; i < 4; i++) {
        int idx = t + i * 256;
        krt[i] = ((const uint4*)kthi)[(size_t)(b * 4096 + (idx >> 4)) * 16 + (idx & 15)];
        krc[i] = ((const uint4*)khi)[(size_t)(b * 128 + (idx >> 3)) * 512 + (idx & 7)];
    }

    for (int tile = 0; tile < 64; tile++) {
        __syncthreads();                  // previous GEMM2 done; K smem writable
#pragma unroll
        for (int i = 0; i < 4; i++) {
            int idx = t + i * 256;
            *(uint4*)(KTh + (idx >> 4) * 68 + (idx & 15) * 4) = krt[i];
            *(uint4*)(Kch + (idx >> 3) * 36 + (idx & 7) * 4)  = krc[i];
        }
        __syncthreads();

        // prefetch next tile (hidden behind GEMM1 + softmax)
        if (tile < 63) {
            int u0n = (tile + 1) * 64;
#pragma unroll
            for (int i = 0; i < 4; i++) {
                int idx = t + i * 256;
                krt[i] = ((const uint4*)kthi)[(size_t)(b * 4096 + u0n + (idx >> 4)) * 16 + (idx & 15)];
                krc[i] = ((const uint4*)khi)[(size_t)(b * 128 + (idx >> 3)) * 512 + (tile + 1) * 8 + (idx & 7)];
            }
        }

        // ---- GEMM1: S = Ah * KTh ----
        float s[8][4];
#pragma unroll
        for (int n = 0; n < 8; n++)
#pragma unroll
            for (int k = 0; k < 4; k++) s[n][k] = 0.f;
#pragma unroll
        for (int ks = 0; ks < 8; ks++) {
            int r0 = (mrow + g) * 68 + 8 * ks + tq;
            int r1 = r0 + 8 * 68;
            unsigned a0 = Ah[r0], a1 = Ah[r1], a2 = Ah[r0 + 4], a3 = Ah[r1 + 4];
#pragma unroll
            for (int n = 0; n < 8; n++) {
                int bi = (8 * n + g) * 68 + 8 * ks + tq;
                mma_h(s[n], a0, a1, a2, a3, KTh[bi], KTh[bi + 4]);
            }
        }
        // ---- scatter exp(S) -> SsT[u][m] (stride 132, conflict-free) ----
#pragma unroll
        for (int n = 0; n < 8; n++) {
            int ub = 8 * n + 2 * tq;
            SsT[ub * 132 + mrow + g]           = __expf(s[n][0]);
            SsT[(ub + 1) * 132 + mrow + g]     = __expf(s[n][1]);
            SsT[ub * 132 + mrow + g + 8]       = __expf(s[n][2]);
            SsT[(ub + 1) * 132 + mrow + g + 8] = __expf(s[n][3]);
        }
        __syncthreads();

        // ---- column sums per w-half via shfl; rsm = 1/sum ----
        {
            int u = wid * 8 + (lane & 7);
            int q4 = lane >> 3;                       // m-quarter
            const float* base = SsT + u * 132 + q4 * 32;
            float ps = 0.f;
#pragma unroll
            for (int j = 0; j < 32; j++) ps += base[(j + q4) & 31];
            ps += __shfl_xor_sync(0xffffffffu, ps, 8);   // combine quarter pairs
            if (!(q4 & 1)) rsm[(q4 >> 1) * 64 + u] = 1.f / ps;
        }
        __syncthreads();

        // ---- P = E * rs -> fp16 round -> Ph[m][u] ----
        {
            int m = t >> 1, uh = (t & 1) * 32, hf = m >> 6;
            const float* rp = rsm + hf * 64;
            unsigned* ph = Ph + m * 36 + (uh >> 1);
#pragma unroll
            for (int j = 0; j < 16; j++) {
                int u = uh + 2 * j;
                ph[j] = packh2(SsT[u * 132 + m] * rp[u],
                               SsT[(u + 1) * 132 + m] * rp[u + 1]);
            }
        }
        __syncthreads();

        // ---- GEMM2: O += Ph * Kch ----
#pragma unroll
        for (int ks = 0; ks < 4; ks++) {
            int r0 = (mrow + g) * 36 + 8 * ks + tq;
            int r1 = r0 + 8 * 36;
            unsigned p0 = Ph[r0], p1 = Ph[r1], p2 = Ph[r0 + 4], p3 = Ph[r1 + 4];
#pragma unroll
            for (int n = 0; n < 16; n++) {
                int bi = (8 * n + g) * 36 + 8 * ks + tq;
                mma_h(o[n], p0, p1, p2, p3, Kch[bi], Kch[bi + 4]);
            }
        }
    }

    {
        size_t base = (size_t)(b * 64 + 2 * wp + (mrow >> 6)) * 64;
        int hrow = (mrow & 63) + g;
        float* r0 = oT + (base + hrow) * 128;
        float* r1 = oT + (base + hrow + 8) * 128;
#pragma unroll
        for (int n = 0; n < 16; n++) {
            *(float2*)(r0 + 8 * n + 2 * tq) = make_float2(o[n][0], o[n][1]);
            *(float2*)(r1 + 8 * n + 2 * tq) = make_float2(o[n][2], o[n][3]);
        }
    }
}

// ------------------------- launch -------------------------
extern "C" void kernel_launch(void* const* d_in, const int* in_sizes, int n_in,
                              void* d_out, int out_size) {
    const float* x    = (const float*)d_in[0];
    const float* tt   = (const float*)d_in[1];
    const int*   aim  = (const int*)d_in[2];
    const float* cond = (const float*)d_in[3];
    const float* g1s  = (const float*)d_in[4];
    const float* g1b  = (const float*)d_in[5];
    const float* c1w  = (const float*)d_in[6];
    const float* c1b  = (const float*)d_in[7];
    const float* mw   = (const float*)d_in[8];
    const float* mb   = (const float*)d_in[9];
    const float* cw   = (const float*)d_in[10];
    const float* cbi  = (const float*)d_in[11];
    const float* g2s  = (const float*)d_in[12];
    const float* g2b  = (const float*)d_in[13];
    const float* c2w  = (const float*)d_in[14];
    const float* c2b  = (const float*)d_in[15];
    const float* emb  = (const float*)d_in[16];
    float* out = (float*)d_out;

    float *h1, *h2, *oT, *temb, *mean, *rstd;
    __half *h1T, *khi, *kthi, *athi, *wh;
    cudaGetSymbolAddress((void**)&h1,   g_h1);
    cudaGetSymbolAddress((void**)&h2,   g_h2);
    cudaGetSymbolAddress((void**)&oT,   g_oT);
    cudaGetSymbolAddress((void**)&temb, g_temb);
    cudaGetSymbolAddress((void**)&mean, g_mean);
    cudaGetSymbolAddress((void**)&rstd, g_rstd);
    cudaGetSymbolAddress((void**)&h1T,  g_h1T);
    cudaGetSymbolAddress((void**)&khi,  g_khi);
    cudaGetSymbolAddress((void**)&kthi, g_kthi);
    cudaGetSymbolAddress((void**)&athi, g_athi);
    cudaGetSymbolAddress((void**)&wh,   g_wh);

    cudaFuncSetAttribute(attn_mma_k, cudaFuncAttributeMaxDynamicSharedMemorySize, ATTN_SMEM);
    cudaFuncSetAttribute(conv_mma_k<0>, cudaFuncAttributeMaxDynamicSharedMemorySize, CONV_SMEM);
    cudaFuncSetAttribute(conv_mma_k<1>, cudaFuncAttributeMaxDynamicSharedMemorySize, CONV_SMEM);
    cudaFuncSetAttribute(cond1x1s_k, cudaFuncAttributeMaxDynamicSharedMemorySize, COND_SMEM);

    gn_stats_k<<<128, 256>>>(x, mean, rstd);
    gnact_k<<<dim3(64, 4), 256>>>(x, mean, rstd, g1s, g1b, athi);
    wround_k<<<576, 256>>>(c1w, wh);
    temb_k<<<dim3(16, 4), 256>>>(tt, mw, mb, temb);
    conv_mma_k<0><<<dim3(64, 4), 256, CONV_SMEM>>>(athi, wh, c1b, temb, nullptr, h1);
    cond1x1s_k<<<dim3(64, 4), 256, COND_SMEM>>>(cond, cw, cbi, khi, kthi);
    transpose_k<<<dim3(64, 4), 256>>>(h1, h1T);
    attn_mma_k<<<dim3(32, 4), 256, ATTN_SMEM>>>(h1T, khi, kthi, oT);
    transadd_k<<<dim3(64, 4), 256>>>(h1, emb, aim, oT, h2);
    gn_stats_k<<<128, 256>>>(h2, mean, rstd);
    gnact_k<<<dim3(64, 4), 256>>>(h2, mean, rstd, g2s, g2b, athi);
    wround_k<<<576, 256>>>(c2w, wh);
    conv_mma_k<1><<<dim3(64, 4), 256, CONV_SMEM>>>(athi, wh, c2b, nullptr, x, out);
}